// round 2
// baseline (speedup 1.0000x reference)
#include <cuda_runtime.h>
#include <math.h>

// Problem constants
#define BATCH 16
#define CIN   256
#define HWN   4096          // 64*64
#define C3    768           // 3*TOTAL
#define CATT  512           // 2*TOTAL (attention output channels)
#define NGRP  64            // attention groups
#define PWG   96            // grouped-pw groups

// Scratch (static device memory — no allocation at runtime)
__device__ float g_qkv[BATCH * C3 * HWN];   // 201 MB
__device__ float g_agg[BATCH * C3 * HWN];   // 201 MB
__device__ float g_att[BATCH * CATT * HWN]; // 134 MB

// ---------------------------------------------------------------------------
// Generic batched SGEMM: C[b] = A (MxK, shared across batch) * B[b] (KxN)
// 128x128 tile, BK=8, 256 threads, 8x8 per-thread microtile.
// Optional per-row BN affine epilogue (gamma/beta/mean/var != nullptr).
// Requires M%128==0, N%128==0, K%8==0, all pointers 16B aligned.
// ---------------------------------------------------------------------------
__global__ __launch_bounds__(256) void sgemm128(
    const float* __restrict__ A,
    const float* __restrict__ Bg,
    float* __restrict__ Cg,
    int M, int N, int K,
    const float* __restrict__ gamma,
    const float* __restrict__ beta,
    const float* __restrict__ mean,
    const float* __restrict__ var)
{
    const int b = blockIdx.z;
    const float* B = Bg + (size_t)b * K * N;
    float*       C = Cg + (size_t)b * M * N;

    const int m0 = blockIdx.y * 128;
    const int n0 = blockIdx.x * 128;
    const int tid = threadIdx.x;

    __shared__ float As[8][128];
    __shared__ float Bs[8][128];

    const int aRow = tid >> 1;          // 0..127
    const int aCol = (tid & 1) << 2;    // 0 or 4
    const int bRow = tid >> 5;          // 0..7
    const int bCol = (tid & 31) << 2;   // 0..124

    const int tx = (tid & 15) << 3;     // col offset of microtile
    const int ty = (tid >> 4) << 3;     // row offset of microtile

    float acc[8][8];
#pragma unroll
    for (int i = 0; i < 8; i++)
#pragma unroll
        for (int j = 0; j < 8; j++) acc[i][j] = 0.f;

    const float* Aptr = A + (size_t)(m0 + aRow) * K + aCol;
    const float* Bptr = B + (size_t)bRow * N + n0 + bCol;

    for (int k0 = 0; k0 < K; k0 += 8) {
        float4 av = *(const float4*)(Aptr + k0);
        As[aCol + 0][aRow] = av.x;
        As[aCol + 1][aRow] = av.y;
        As[aCol + 2][aRow] = av.z;
        As[aCol + 3][aRow] = av.w;
        float4 bv = *(const float4*)(Bptr + (size_t)k0 * N);
        *(float4*)&Bs[bRow][bCol] = bv;
        __syncthreads();

#pragma unroll
        for (int k = 0; k < 8; k++) {
            float am[8], bn[8];
            *(float4*)&am[0] = *(const float4*)&As[k][ty];
            *(float4*)&am[4] = *(const float4*)&As[k][ty + 4];
            *(float4*)&bn[0] = *(const float4*)&Bs[k][tx];
            *(float4*)&bn[4] = *(const float4*)&Bs[k][tx + 4];
#pragma unroll
            for (int i = 0; i < 8; i++)
#pragma unroll
                for (int j = 0; j < 8; j++)
                    acc[i][j] = fmaf(am[i], bn[j], acc[i][j]);
        }
        __syncthreads();
    }

#pragma unroll
    for (int i = 0; i < 8; i++) {
        const int row = m0 + ty + i;
        float s = 1.f, bi = 0.f;
        if (gamma) {
            float iv = gamma[row] * rsqrtf(var[row] + 1e-5f);
            s = iv;
            bi = beta[row] - mean[row] * iv;
        }
        float* crow = C + (size_t)row * N + n0 + tx;
#pragma unroll
        for (int j = 0; j < 8; j += 4) {
            float4 v;
            v.x = acc[i][j + 0] * s + bi;
            v.y = acc[i][j + 1] * s + bi;
            v.z = acc[i][j + 2] * s + bi;
            v.w = acc[i][j + 3] * s + bi;
            *(float4*)(crow + j) = v;
        }
    }
}

// ---------------------------------------------------------------------------
// Depthwise 5x5 conv, pad 2, 64x64 plane per block (b*C3+c planes).
// ---------------------------------------------------------------------------
__global__ __launch_bounds__(256) void dwconv5(
    const float* __restrict__ in,
    const float* __restrict__ w,
    float* __restrict__ out)
{
    const int plane = blockIdx.x;             // b*C3 + c
    const int c = plane % C3;
    const float* ip = in + (size_t)plane * HWN;
    float*       op = out + (size_t)plane * HWN;

    __shared__ float tile[68 * 68];
    __shared__ float wt[25];

    const int tid = threadIdx.x;
    if (tid < 25) wt[tid] = w[c * 25 + tid];

    for (int idx = tid; idx < 68 * 68; idx += 256) {
        int sy = idx / 68, sx = idx - sy * 68;
        int gy = sy - 2, gx = sx - 2;
        float v = 0.f;
        if ((unsigned)gy < 64u && (unsigned)gx < 64u) v = ip[gy * 64 + gx];
        tile[idx] = v;
    }
    __syncthreads();

    for (int p = tid; p < HWN; p += 256) {
        int y = p >> 6, x = p & 63;
        float s = 0.f;
#pragma unroll
        for (int dy = 0; dy < 5; dy++)
#pragma unroll
            for (int dx = 0; dx < 5; dx++)
                s = fmaf(tile[(y + dy) * 68 + (x + dx)], wt[dy * 5 + dx], s);
        op[p] = s;
    }
}

// ---------------------------------------------------------------------------
// Grouped 1x1 conv (96 groups of 8 channels), in place on agg.
// One block per (b, g).
// ---------------------------------------------------------------------------
__global__ __launch_bounds__(256) void grouped_pw(
    float* __restrict__ agg,
    const float* __restrict__ wpw)   // [g][o][c] flattened (g*64 + o*8 + c)
{
    const int bg = blockIdx.x;                  // b*PWG + g
    const int g = bg % PWG;
    const int b = bg / PWG;
    float* p = agg + ((size_t)b * C3 + (size_t)g * 8) * HWN;

    __shared__ float w[64];
    if (threadIdx.x < 64) w[threadIdx.x] = wpw[g * 64 + threadIdx.x];
    __syncthreads();

    for (int n = threadIdx.x; n < HWN; n += 256) {
        float a[8];
#pragma unroll
        for (int c = 0; c < 8; c++) a[c] = p[(size_t)c * HWN + n];
#pragma unroll
        for (int o = 0; o < 8; o++) {
            float s = 0.f;
#pragma unroll
            for (int c = 0; c < 8; c++) s = fmaf(w[o * 8 + c], a[c], s);
            p[(size_t)o * HWN + n] = s;
        }
    }
}

// ---------------------------------------------------------------------------
// ReLU linear attention. One block per (b, g); G=64 groups of 24 channels
// taken from concat([qkv, agg]) along channels.
// ---------------------------------------------------------------------------
__global__ __launch_bounds__(256) void relu_lin_att(
    const float* __restrict__ qkv,
    const float* __restrict__ agg,
    float* __restrict__ outp)
{
    const int bg = blockIdx.x;         // b*NGRP + g
    const int b = bg >> 6;
    const int g = bg & 63;
    const float* base = (g < 32)
        ? qkv + ((size_t)b * C3 + (size_t)g * 24) * HWN
        : agg + ((size_t)b * C3 + (size_t)(g - 32) * 24) * HWN;

    __shared__ float kvs[72];
    const int tid = threadIdx.x;
    if (tid < 72) kvs[tid] = 0.f;
    __syncthreads();

    float kv[72];
#pragma unroll
    for (int i = 0; i < 72; i++) kv[i] = 0.f;

    // Pass 1: kv[d][e] = sum_n relu(k_d) * v_e ; kv[d][8] = sum_n relu(k_d)
    for (int n = tid; n < HWN; n += 256) {
        float kk[8], vv[8];
#pragma unroll
        for (int d = 0; d < 8; d++) kk[d] = fmaxf(base[(size_t)(8 + d) * HWN + n], 0.f);
#pragma unroll
        for (int d = 0; d < 8; d++) vv[d] = base[(size_t)(16 + d) * HWN + n];
#pragma unroll
        for (int d = 0; d < 8; d++) {
#pragma unroll
            for (int e = 0; e < 8; e++) kv[d * 9 + e] = fmaf(kk[d], vv[e], kv[d * 9 + e]);
            kv[d * 9 + 8] += kk[d];
        }
    }

#pragma unroll
    for (int i = 0; i < 72; i++) {
        float v = kv[i];
        v += __shfl_xor_sync(0xffffffffu, v, 16);
        v += __shfl_xor_sync(0xffffffffu, v, 8);
        v += __shfl_xor_sync(0xffffffffu, v, 4);
        v += __shfl_xor_sync(0xffffffffu, v, 2);
        v += __shfl_xor_sync(0xffffffffu, v, 1);
        if ((tid & 31) == 0) atomicAdd(&kvs[i], v);
    }
    __syncthreads();

    // Pass 2: out_e(n) = sum_d relu(q_d) kv[d][e] ; normalize by denominator
    float* og = outp + ((size_t)b * CATT + (size_t)g * 8) * HWN;
    for (int n = tid; n < HWN; n += 256) {
        float qd[8];
#pragma unroll
        for (int d = 0; d < 8; d++) qd[d] = fmaxf(base[(size_t)d * HWN + n], 0.f);
        float den = 0.f;
#pragma unroll
        for (int d = 0; d < 8; d++) den = fmaf(qd[d], kvs[d * 9 + 8], den);
        float rden = 1.f / (den + 1e-15f);
#pragma unroll
        for (int e = 0; e < 8; e++) {
            float num = 0.f;
#pragma unroll
            for (int d = 0; d < 8; d++) num = fmaf(qd[d], kvs[d * 9 + e], num);
            og[(size_t)e * HWN + n] = num * rden;
        }
    }
}

// ---------------------------------------------------------------------------
// Launch
// ---------------------------------------------------------------------------
extern "C" void kernel_launch(void* const* d_in, const int* in_sizes, int n_in,
                              void* d_out, int out_size)
{
    const float* x      = (const float*)d_in[0];
    const float* w_qkv  = (const float*)d_in[1];
    const float* w_dw   = (const float*)d_in[2];
    const float* w_pw   = (const float*)d_in[3];
    const float* w_proj = (const float*)d_in[4];
    const float* gamma  = (const float*)d_in[5];
    const float* beta   = (const float*)d_in[6];
    const float* mean   = (const float*)d_in[7];
    const float* var    = (const float*)d_in[8];
    float* out = (float*)d_out;

    float *qkv_s = nullptr, *agg_s = nullptr, *att_s = nullptr;
    cudaGetSymbolAddress((void**)&qkv_s, g_qkv);
    cudaGetSymbolAddress((void**)&agg_s, g_agg);
    cudaGetSymbolAddress((void**)&att_s, g_att);

    // 1) qkv = w_qkv @ x   (per batch: 768x256 * 256x4096)
    {
        dim3 grid(HWN / 128, C3 / 128, BATCH);   // (32, 6, 16)
        sgemm128<<<grid, 256>>>(w_qkv, x, qkv_s, C3, HWN, CIN,
                                nullptr, nullptr, nullptr, nullptr);
    }

    // 2) depthwise 5x5 -> agg
    dwconv5<<<BATCH * C3, 256>>>(qkv_s, w_dw, agg_s);

    // 3) grouped pointwise (in place on agg)
    grouped_pw<<<BATCH * PWG, 256>>>(agg_s, w_pw);

    // 4) relu linear attention over concat([qkv, agg])
    relu_lin_att<<<BATCH * NGRP, 256>>>(qkv_s, agg_s, att_s);

    // 5) proj + BN: out = BN(w_proj @ att)  -- M=256 -> exactly 2 row tiles
    {
        dim3 grid(HWN / 128, 256 / 128, BATCH);  // (32, 2, 16)
        sgemm128<<<grid, 256>>>(w_proj, att_s, out, 256, HWN, CATT,
                                gamma, beta, mean, var);
    }
}

// round 5
// speedup vs baseline: 1.2605x; 1.2605x over previous
#include <cuda_runtime.h>
#include <cuda_bf16.h>
#include <cstdint>

// Problem constants
#define BATCH 16
#define CIN   256
#define HWN   4096          // 64*64
#define C3    768           // 3*TOTAL
#define CATT  512           // 2*TOTAL
#define PWG   96

// ---------------------------------------------------------------------------
// Scratch (static device memory)
// ---------------------------------------------------------------------------
__device__ float g_qkv[BATCH * C3 * HWN];               // 201 MB
__device__ float g_agg[BATCH * C3 * HWN];               // 201 MB
__device__ float g_xT_hi[BATCH * HWN * CIN];            // 67 MB (tf32 bits)
__device__ float g_xT_lo[BATCH * HWN * CIN];            // 67 MB
__device__ __nv_bfloat16 g_attT_hi[BATCH * HWN * CATT]; // 67 MB
__device__ __nv_bfloat16 g_attT_lo[BATCH * HWN * CATT];
__device__ float g_wqkv_hi[C3 * CIN];
__device__ float g_wqkv_lo[C3 * CIN];
__device__ __nv_bfloat16 g_wproj_hi[256 * CATT];
__device__ __nv_bfloat16 g_wproj_lo[256 * CATT];

// ---------------------------------------------------------------------------
// Helpers
// ---------------------------------------------------------------------------
__device__ __forceinline__ uint32_t smem_u32(const void* p) {
    uint32_t a;
    asm("{ .reg .u64 t; cvta.to.shared.u64 t, %1; cvt.u32.u64 %0, t; }" : "=r"(a) : "l"(p));
    return a;
}
__device__ __forceinline__ void ldmx4(uint32_t* r, uint32_t addr) {
    asm volatile("ldmatrix.sync.aligned.m8n8.x4.shared.b16 {%0,%1,%2,%3}, [%4];"
                 : "=r"(r[0]), "=r"(r[1]), "=r"(r[2]), "=r"(r[3]) : "r"(addr));
}
__device__ __forceinline__ void ldmx2(uint32_t* r, uint32_t addr) {
    asm volatile("ldmatrix.sync.aligned.m8n8.x2.shared.b16 {%0,%1}, [%2];"
                 : "=r"(r[0]), "=r"(r[1]) : "r"(addr));
}
__device__ __forceinline__ void mma_bf16(float* d, const uint32_t* a, const uint32_t* b) {
    asm volatile(
        "mma.sync.aligned.m16n8k16.row.col.f32.bf16.bf16.f32 "
        "{%0,%1,%2,%3}, {%4,%5,%6,%7}, {%8,%9}, {%0,%1,%2,%3};"
        : "+f"(d[0]), "+f"(d[1]), "+f"(d[2]), "+f"(d[3])
        : "r"(a[0]), "r"(a[1]), "r"(a[2]), "r"(a[3]), "r"(b[0]), "r"(b[1]));
}
__device__ __forceinline__ void mma_tf32(float* d, const uint32_t* a, const uint32_t* b) {
    asm volatile(
        "mma.sync.aligned.m16n8k8.row.col.f32.tf32.tf32.f32 "
        "{%0,%1,%2,%3}, {%4,%5,%6,%7}, {%8,%9}, {%0,%1,%2,%3};"
        : "+f"(d[0]), "+f"(d[1]), "+f"(d[2]), "+f"(d[3])
        : "r"(a[0]), "r"(a[1]), "r"(a[2]), "r"(a[3]), "r"(b[0]), "r"(b[1]));
}
__device__ __forceinline__ float tf32_rna(float v) {
    uint32_t o;
    asm("cvt.rna.tf32.f32 %0, %1;" : "=r"(o) : "f"(v));
    return __uint_as_float(o);
}

// ---------------------------------------------------------------------------
// Splits
// ---------------------------------------------------------------------------
__global__ void split_bf16(const float* __restrict__ src,
                           __nv_bfloat16* __restrict__ hi,
                           __nv_bfloat16* __restrict__ lo, int n) {
    int i = blockIdx.x * 256 + threadIdx.x;
    if (i < n) {
        float v = src[i];
        __nv_bfloat16 h = __float2bfloat16(v);
        hi[i] = h;
        lo[i] = __float2bfloat16(v - __bfloat162float(h));
    }
}
__global__ void split_tf32(const float* __restrict__ src,
                           float* __restrict__ hi, float* __restrict__ lo, int n) {
    int i = blockIdx.x * 256 + threadIdx.x;
    if (i < n) {
        float v = src[i];
        float h = tf32_rna(v);
        hi[i] = h;
        lo[i] = tf32_rna(v - h);
    }
}

// ---------------------------------------------------------------------------
// Transpose + tf32-split x: [b][c][n] fp32 -> xT_hi/lo [b][n][c]
// ---------------------------------------------------------------------------
__global__ __launch_bounds__(256) void transpose_split_x(
    const float* __restrict__ x, float* __restrict__ xhi, float* __restrict__ xlo) {
    const int b = blockIdx.z;
    const int c0 = blockIdx.y * 64;
    const int n0 = blockIdx.x * 32;
    __shared__ float s[64][33];
    const int tid = threadIdx.x;
#pragma unroll
    for (int i = 0; i < 8; i++) {
        int u = tid + 256 * i;
        int cc = u >> 5, nn = u & 31;
        s[cc][nn] = x[((size_t)b * CIN + c0 + cc) * HWN + n0 + nn];
    }
    __syncthreads();
#pragma unroll
    for (int i = 0; i < 8; i++) {
        int u = tid + 256 * i;
        int cc = u & 63, nn = u >> 6;
        float v = s[cc][nn];
        float h = tf32_rna(v);
        size_t idx = ((size_t)b * HWN + n0 + nn) * CIN + c0 + cc;
        xhi[idx] = h;
        xlo[idx] = tf32_rna(v - h);
    }
}

// ---------------------------------------------------------------------------
// tf32 3-term split GEMM via mma.sync.m16n8k8:
//   C[b][m][n] = sum_k A[m][k]*B[b][n][k]   (terms hh + hl + lh)
// CTA 128x128, BK=16, 8 warps (2x4), warp 64x32 (4x4 m16n8 tiles).
// ---------------------------------------------------------------------------
#define TLDS 20   // smem row stride in floats (16 + 4 pad)

__global__ __launch_bounds__(256, 2) void gemm_tf32(
    const float* __restrict__ Ahi, const float* __restrict__ Alo,
    const float* __restrict__ Bhi, const float* __restrict__ Blo,
    float* __restrict__ Cg, int M, int K) {
    __shared__ float As_hi[128 * TLDS];
    __shared__ float As_lo[128 * TLDS];
    __shared__ float Bs_hi[128 * TLDS];
    __shared__ float Bs_lo[128 * TLDS];

    const int tid = threadIdx.x;
    const int wid = tid >> 5;
    const int lane = tid & 31;

    const int b = blockIdx.z;
    const int m0 = blockIdx.y * 128;
    const int n0 = blockIdx.x * 128;

    const float* Bh = Bhi + (size_t)b * HWN * K;
    const float* Bl = Blo + (size_t)b * HWN * K;

    const int wm = (wid >> 2) * 64;
    const int wn = (wid & 3) * 32;

    const int qr = lane >> 2;    // 0..7
    const int qc = lane & 3;     // 0..3

    float acc[4][4][4];
#pragma unroll
    for (int mt = 0; mt < 4; mt++)
#pragma unroll
        for (int nt = 0; nt < 4; nt++)
#pragma unroll
            for (int r = 0; r < 4; r++) acc[mt][nt][r] = 0.f;

    for (int kc = 0; kc < K; kc += 16) {
        // load tiles (128 rows x 16 floats, hi+lo, A and B)
#pragma unroll
        for (int i = 0; i < 2; i++) {
            int u = tid + 256 * i;      // 0..511
            int row = u >> 2;
            int c4 = (u & 3) << 2;      // 0,4,8,12
            size_t sa = (size_t)(m0 + row) * K + kc + c4;
            *(float4*)&As_hi[row * TLDS + c4] = *(const float4*)(Ahi + sa);
            *(float4*)&As_lo[row * TLDS + c4] = *(const float4*)(Alo + sa);
            size_t sb = (size_t)(n0 + row) * K + kc + c4;
            *(float4*)&Bs_hi[row * TLDS + c4] = *(const float4*)(Bh + sb);
            *(float4*)&Bs_lo[row * TLDS + c4] = *(const float4*)(Bl + sb);
        }
        __syncthreads();

#pragma unroll
        for (int kk = 0; kk < 16; kk += 8) {
            // B fragments for all 4 n-tiles (hi and lo)
            uint32_t bh[4][2], bl[4][2];
#pragma unroll
            for (int nt = 0; nt < 4; nt++) {
                int nbase = (wn + nt * 8 + qr) * TLDS + kk + qc;
                bh[nt][0] = __float_as_uint(Bs_hi[nbase]);
                bh[nt][1] = __float_as_uint(Bs_hi[nbase + 4]);
                bl[nt][0] = __float_as_uint(Bs_lo[nbase]);
                bl[nt][1] = __float_as_uint(Bs_lo[nbase + 4]);
            }
#pragma unroll
            for (int mt = 0; mt < 4; mt++) {
                int abase = (wm + mt * 16 + qr) * TLDS + kk + qc;
                uint32_t ah[4], al[4];
                ah[0] = __float_as_uint(As_hi[abase]);
                ah[1] = __float_as_uint(As_hi[abase + 8 * TLDS]);
                ah[2] = __float_as_uint(As_hi[abase + 4]);
                ah[3] = __float_as_uint(As_hi[abase + 8 * TLDS + 4]);
                al[0] = __float_as_uint(As_lo[abase]);
                al[1] = __float_as_uint(As_lo[abase + 8 * TLDS]);
                al[2] = __float_as_uint(As_lo[abase + 4]);
                al[3] = __float_as_uint(As_lo[abase + 8 * TLDS + 4]);
#pragma unroll
                for (int nt = 0; nt < 4; nt++) {
                    mma_tf32(acc[mt][nt], ah, bh[nt]);   // hh
                    mma_tf32(acc[mt][nt], ah, bl[nt]);   // hl
                    mma_tf32(acc[mt][nt], al, bh[nt]);   // lh
                }
            }
        }
        __syncthreads();
    }

    // epilogue (m16n8 C layout)
#pragma unroll
    for (int mt = 0; mt < 4; mt++) {
        const int row0 = m0 + wm + mt * 16 + qr;
        const int row1 = row0 + 8;
        float* c0p = Cg + ((size_t)b * M + row0) * HWN + n0 + wn;
        float* c1p = Cg + ((size_t)b * M + row1) * HWN + n0 + wn;
        const int coff = qc << 1;
#pragma unroll
        for (int nt = 0; nt < 4; nt++) {
            *(float2*)(c0p + nt * 8 + coff) = make_float2(acc[mt][nt][0], acc[mt][nt][1]);
            *(float2*)(c1p + nt * 8 + coff) = make_float2(acc[mt][nt][2], acc[mt][nt][3]);
        }
    }
}

// ---------------------------------------------------------------------------
// bf16 3-term split GEMM (proj only): identical to R4's kernel.
// ---------------------------------------------------------------------------
#define BK  32
#define LDS 40

__global__ __launch_bounds__(256, 2) void gemm_mma(
    const __nv_bfloat16* __restrict__ Ahi, const __nv_bfloat16* __restrict__ Alo,
    const __nv_bfloat16* __restrict__ Bhi, const __nv_bfloat16* __restrict__ Blo,
    float* __restrict__ Cg, int M, int K,
    const float* __restrict__ gamma, const float* __restrict__ beta,
    const float* __restrict__ mean, const float* __restrict__ var) {
    __shared__ __nv_bfloat16 As_hi[128 * LDS];
    __shared__ __nv_bfloat16 As_lo[128 * LDS];
    __shared__ __nv_bfloat16 Bs_hi[128 * LDS];
    __shared__ __nv_bfloat16 Bs_lo[128 * LDS];

    const int tid = threadIdx.x;
    const int wid = tid >> 5;
    const int lane = tid & 31;

    const int b = blockIdx.z;
    const int m0 = blockIdx.y * 128;
    const int n0 = blockIdx.x * 128;

    const __nv_bfloat16* Bh = Bhi + (size_t)b * HWN * K;
    const __nv_bfloat16* Bl = Blo + (size_t)b * HWN * K;

    const int wm = (wid >> 2) * 64;
    const int wn = (wid & 3) * 32;

    const int ar = lane & 15, ac = (lane >> 4) << 3;
    const int br = lane & 7,  bc = ((lane >> 3) & 1) << 3;

    float acc[4][4][4];
#pragma unroll
    for (int mt = 0; mt < 4; mt++)
#pragma unroll
        for (int nt = 0; nt < 4; nt++)
#pragma unroll
            for (int r = 0; r < 4; r++) acc[mt][nt][r] = 0.f;

    for (int kc = 0; kc < K; kc += BK) {
#pragma unroll
        for (int i = 0; i < 2; i++) {
            int u = tid + 256 * i;
            int row = u >> 2;
            int cu = (u & 3) << 3;
            size_t sa = (size_t)(m0 + row) * K + kc + cu;
            *(uint4*)&As_hi[row * LDS + cu] = *(const uint4*)(Ahi + sa);
            *(uint4*)&As_lo[row * LDS + cu] = *(const uint4*)(Alo + sa);
            size_t sb = (size_t)(n0 + row) * K + kc + cu;
            *(uint4*)&Bs_hi[row * LDS + cu] = *(const uint4*)(Bh + sb);
            *(uint4*)&Bs_lo[row * LDS + cu] = *(const uint4*)(Bl + sb);
        }
        __syncthreads();

#pragma unroll
        for (int kk = 0; kk < BK; kk += 16) {
            uint32_t ah[4][4], bhf[4][2];
#pragma unroll
            for (int mt = 0; mt < 4; mt++)
                ldmx4(ah[mt], smem_u32(&As_hi[(wm + mt * 16 + ar) * LDS + kk + ac]));
#pragma unroll
            for (int nt = 0; nt < 4; nt++)
                ldmx2(bhf[nt], smem_u32(&Bs_hi[(wn + nt * 8 + br) * LDS + kk + bc]));
#pragma unroll
            for (int mt = 0; mt < 4; mt++)
#pragma unroll
                for (int nt = 0; nt < 4; nt++)
                    mma_bf16(acc[mt][nt], ah[mt], bhf[nt]);

            uint32_t al[4][4];
#pragma unroll
            for (int mt = 0; mt < 4; mt++)
                ldmx4(al[mt], smem_u32(&As_lo[(wm + mt * 16 + ar) * LDS + kk + ac]));
#pragma unroll
            for (int mt = 0; mt < 4; mt++)
#pragma unroll
                for (int nt = 0; nt < 4; nt++)
                    mma_bf16(acc[mt][nt], al[mt], bhf[nt]);

            uint32_t blf[4][2];
#pragma unroll
            for (int nt = 0; nt < 4; nt++)
                ldmx2(blf[nt], smem_u32(&Bs_lo[(wn + nt * 8 + br) * LDS + kk + bc]));
#pragma unroll
            for (int mt = 0; mt < 4; mt++)
#pragma unroll
                for (int nt = 0; nt < 4; nt++)
                    mma_bf16(acc[mt][nt], ah[mt], blf[nt]);
        }
        __syncthreads();
    }

#pragma unroll
    for (int mt = 0; mt < 4; mt++) {
        const int row0 = m0 + wm + mt * 16 + (lane >> 2);
        const int row1 = row0 + 8;
        float s0 = 1.f, o0 = 0.f, s1 = 1.f, o1 = 0.f;
        if (gamma) {
            float iv0 = gamma[row0] * rsqrtf(var[row0] + 1e-5f);
            s0 = iv0; o0 = beta[row0] - mean[row0] * iv0;
            float iv1 = gamma[row1] * rsqrtf(var[row1] + 1e-5f);
            s1 = iv1; o1 = beta[row1] - mean[row1] * iv1;
        }
        float* c0p = Cg + ((size_t)b * M + row0) * HWN + n0 + wn;
        float* c1p = Cg + ((size_t)b * M + row1) * HWN + n0 + wn;
        const int coff = ((lane & 3) << 1);
#pragma unroll
        for (int nt = 0; nt < 4; nt++) {
            float2 v0, v1;
            v0.x = acc[mt][nt][0] * s0 + o0;
            v0.y = acc[mt][nt][1] * s0 + o0;
            v1.x = acc[mt][nt][2] * s1 + o1;
            v1.y = acc[mt][nt][3] * s1 + o1;
            *(float2*)(c0p + nt * 8 + coff) = v0;
            *(float2*)(c1p + nt * 8 + coff) = v1;
        }
    }
}

// ---------------------------------------------------------------------------
// Depthwise 5x5 conv, pad 2
// ---------------------------------------------------------------------------
__global__ __launch_bounds__(256) void dwconv5(
    const float* __restrict__ in, const float* __restrict__ w, float* __restrict__ out) {
    const int plane = blockIdx.x;
    const int c = plane % C3;
    const float* ip = in + (size_t)plane * HWN;
    float* op = out + (size_t)plane * HWN;

    __shared__ float tile[68 * 68];
    __shared__ float wt[25];
    const int tid = threadIdx.x;
    if (tid < 25) wt[tid] = w[c * 25 + tid];
    for (int idx = tid; idx < 68 * 68; idx += 256) {
        int sy = idx / 68, sx = idx - sy * 68;
        int gy = sy - 2, gx = sx - 2;
        float v = 0.f;
        if ((unsigned)gy < 64u && (unsigned)gx < 64u) v = ip[gy * 64 + gx];
        tile[idx] = v;
    }
    __syncthreads();
    for (int p = tid; p < HWN; p += 256) {
        int y = p >> 6, x = p & 63;
        float s = 0.f;
#pragma unroll
        for (int dy = 0; dy < 5; dy++)
#pragma unroll
            for (int dx = 0; dx < 5; dx++)
                s = fmaf(tile[(y + dy) * 68 + (x + dx)], wt[dy * 5 + dx], s);
        op[p] = s;
    }
}

// ---------------------------------------------------------------------------
// Grouped 1x1 conv (96 groups of 8 ch), in place on agg
// ---------------------------------------------------------------------------
__global__ __launch_bounds__(256) void grouped_pw(
    float* __restrict__ agg, const float* __restrict__ wpw) {
    const int bg = blockIdx.x;
    const int g = bg % PWG;
    const int b = bg / PWG;
    float* p = agg + ((size_t)b * C3 + (size_t)g * 8) * HWN;
    __shared__ float w[64];
    if (threadIdx.x < 64) w[threadIdx.x] = wpw[g * 64 + threadIdx.x];
    __syncthreads();
    for (int n = threadIdx.x; n < HWN; n += 256) {
        float a[8];
#pragma unroll
        for (int c = 0; c < 8; c++) a[c] = p[(size_t)c * HWN + n];
#pragma unroll
        for (int o = 0; o < 8; o++) {
            float s = 0.f;
#pragma unroll
            for (int c = 0; c < 8; c++) s = fmaf(w[o * 8 + c], a[c], s);
            p[(size_t)o * HWN + n] = s;
        }
    }
}

// ---------------------------------------------------------------------------
// ReLU linear attention; writes transposed bf16 hi/lo output (proj B operand)
// ---------------------------------------------------------------------------
__global__ __launch_bounds__(256) void relu_lin_att(
    const float* __restrict__ qkv, const float* __restrict__ agg,
    __nv_bfloat16* __restrict__ ohi, __nv_bfloat16* __restrict__ olo) {
    const int bg = blockIdx.x;
    const int b = bg >> 6;
    const int g = bg & 63;
    const float* base = (g < 32)
        ? qkv + ((size_t)b * C3 + (size_t)g * 24) * HWN
        : agg + ((size_t)b * C3 + (size_t)(g - 32) * 24) * HWN;

    __shared__ float kvs[72];
    const int tid = threadIdx.x;
    if (tid < 72) kvs[tid] = 0.f;
    __syncthreads();

    float kv[72];
#pragma unroll
    for (int i = 0; i < 72; i++) kv[i] = 0.f;

    for (int n = tid; n < HWN; n += 256) {
        float kk[8], vv[8];
#pragma unroll
        for (int d = 0; d < 8; d++) kk[d] = fmaxf(base[(size_t)(8 + d) * HWN + n], 0.f);
#pragma unroll
        for (int d = 0; d < 8; d++) vv[d] = base[(size_t)(16 + d) * HWN + n];
#pragma unroll
        for (int d = 0; d < 8; d++) {
#pragma unroll
            for (int e = 0; e < 8; e++) kv[d * 9 + e] = fmaf(kk[d], vv[e], kv[d * 9 + e]);
            kv[d * 9 + 8] += kk[d];
        }
    }
#pragma unroll
    for (int i = 0; i < 72; i++) {
        float v = kv[i];
        v += __shfl_xor_sync(0xffffffffu, v, 16);
        v += __shfl_xor_sync(0xffffffffu, v, 8);
        v += __shfl_xor_sync(0xffffffffu, v, 4);
        v += __shfl_xor_sync(0xffffffffu, v, 2);
        v += __shfl_xor_sync(0xffffffffu, v, 1);
        if ((tid & 31) == 0) atomicAdd(&kvs[i], v);
    }
    __syncthreads();

    for (int n = tid; n < HWN; n += 256) {
        float qd[8];
#pragma unroll
        for (int d = 0; d < 8; d++) qd[d] = fmaxf(base[(size_t)d * HWN + n], 0.f);
        float den = 0.f;
#pragma unroll
        for (int d = 0; d < 8; d++) den = fmaf(qd[d], kvs[d * 9 + 8], den);
        float rden = 1.f / (den + 1e-15f);
        __align__(16) __nv_bfloat16 hi[8], lo[8];
#pragma unroll
        for (int e = 0; e < 8; e++) {
            float num = 0.f;
#pragma unroll
            for (int d = 0; d < 8; d++) num = fmaf(qd[d], kvs[d * 9 + e], num);
            float v = num * rden;
            __nv_bfloat16 h = __float2bfloat16(v);
            hi[e] = h;
            lo[e] = __float2bfloat16(v - __bfloat162float(h));
        }
        size_t idx = ((size_t)b * HWN + n) * CATT + g * 8;
        *(uint4*)(ohi + idx) = *(const uint4*)hi;
        *(uint4*)(olo + idx) = *(const uint4*)lo;
    }
}

// ---------------------------------------------------------------------------
// Launch
// ---------------------------------------------------------------------------
extern "C" void kernel_launch(void* const* d_in, const int* in_sizes, int n_in,
                              void* d_out, int out_size) {
    const float* x      = (const float*)d_in[0];
    const float* w_qkv  = (const float*)d_in[1];
    const float* w_dw   = (const float*)d_in[2];
    const float* w_pw   = (const float*)d_in[3];
    const float* w_proj = (const float*)d_in[4];
    const float* gamma  = (const float*)d_in[5];
    const float* beta   = (const float*)d_in[6];
    const float* mean   = (const float*)d_in[7];
    const float* var    = (const float*)d_in[8];
    float* out = (float*)d_out;

    float *qkv_s, *agg_s, *xh, *xl, *wqh, *wql;
    __nv_bfloat16 *ah, *al, *wph, *wpl;
    cudaGetSymbolAddress((void**)&qkv_s, g_qkv);
    cudaGetSymbolAddress((void**)&agg_s, g_agg);
    cudaGetSymbolAddress((void**)&xh, g_xT_hi);
    cudaGetSymbolAddress((void**)&xl, g_xT_lo);
    cudaGetSymbolAddress((void**)&ah, g_attT_hi);
    cudaGetSymbolAddress((void**)&al, g_attT_lo);
    cudaGetSymbolAddress((void**)&wqh, g_wqkv_hi);
    cudaGetSymbolAddress((void**)&wql, g_wqkv_lo);
    cudaGetSymbolAddress((void**)&wph, g_wproj_hi);
    cudaGetSymbolAddress((void**)&wpl, g_wproj_lo);

    // 0) weight splits + x transpose/split
    split_tf32<<<(C3 * CIN + 255) / 256, 256>>>(w_qkv, wqh, wql, C3 * CIN);
    split_bf16<<<(256 * CATT + 255) / 256, 256>>>(w_proj, wph, wpl, 256 * CATT);
    {
        dim3 grid(HWN / 32, CIN / 64, BATCH);
        transpose_split_x<<<grid, 256>>>(x, xh, xl);
    }

    // 1) qkv GEMM (tf32 split): M=768, K=256
    {
        dim3 grid(HWN / 128, C3 / 128, BATCH);   // (32, 6, 16)
        gemm_tf32<<<grid, 256>>>(wqh, wql, xh, xl, qkv_s, C3, CIN);
    }

    // 2) depthwise 5x5 -> agg
    dwconv5<<<BATCH * C3, 256>>>(qkv_s, w_dw, agg_s);

    // 3) grouped pointwise (in place)
    grouped_pw<<<BATCH * PWG, 256>>>(agg_s, w_pw);

    // 4) attention -> transposed bf16 hi/lo
    relu_lin_att<<<BATCH * 64, 256>>>(qkv_s, agg_s, ah, al);

    // 5) proj GEMM (bf16 split) + BN: M=256, K=512
    {
        dim3 grid(HWN / 128, 256 / 128, BATCH);  // (32, 2, 16)
        gemm_mma<<<grid, 256>>>(wph, wpl, ah, al, out, 256, CATT,
                                gamma, beta, mean, var);
    }
}

// round 8
// speedup vs baseline: 1.3993x; 1.1102x over previous
#include <cuda_runtime.h>
#include <cuda_bf16.h>
#include <cstdint>

// Problem constants
#define BATCH 16
#define CIN   256
#define HWN   4096          // 64*64
#define C3    768           // 3*TOTAL
#define CATT  512           // 2*TOTAL
#define PWG   96

// ---------------------------------------------------------------------------
// Scratch (static device memory)
// ---------------------------------------------------------------------------
__device__ float g_qkv[BATCH * C3 * HWN];               // 201 MB
__device__ float g_agg[BATCH * C3 * HWN];               // 201 MB
__device__ float g_xT_hi[BATCH * HWN * CIN];            // 67 MB (tf32 bits)
__device__ float g_xT_lo[BATCH * HWN * CIN];            // 67 MB
__device__ __nv_bfloat16 g_attT_hi[BATCH * HWN * CATT]; // 67 MB
__device__ __nv_bfloat16 g_attT_lo[BATCH * HWN * CATT];
__device__ float g_wqkv_hi[C3 * CIN];
__device__ float g_wqkv_lo[C3 * CIN];
__device__ __nv_bfloat16 g_wproj_hi[256 * CATT];
__device__ __nv_bfloat16 g_wproj_lo[256 * CATT];

// ---------------------------------------------------------------------------
// Helpers
// ---------------------------------------------------------------------------
__device__ __forceinline__ uint32_t smem_u32(const void* p) {
    uint32_t a;
    asm("{ .reg .u64 t; cvta.to.shared.u64 t, %1; cvt.u32.u64 %0, t; }" : "=r"(a) : "l"(p));
    return a;
}
__device__ __forceinline__ void ldmx4(uint32_t* r, uint32_t addr) {
    asm volatile("ldmatrix.sync.aligned.m8n8.x4.shared.b16 {%0,%1,%2,%3}, [%4];"
                 : "=r"(r[0]), "=r"(r[1]), "=r"(r[2]), "=r"(r[3]) : "r"(addr));
}
__device__ __forceinline__ void ldmx2(uint32_t* r, uint32_t addr) {
    asm volatile("ldmatrix.sync.aligned.m8n8.x2.shared.b16 {%0,%1}, [%2];"
                 : "=r"(r[0]), "=r"(r[1]) : "r"(addr));
}
__device__ __forceinline__ void mma_bf16(float* d, const uint32_t* a, const uint32_t* b) {
    asm volatile(
        "mma.sync.aligned.m16n8k16.row.col.f32.bf16.bf16.f32 "
        "{%0,%1,%2,%3}, {%4,%5,%6,%7}, {%8,%9}, {%0,%1,%2,%3};"
        : "+f"(d[0]), "+f"(d[1]), "+f"(d[2]), "+f"(d[3])
        : "r"(a[0]), "r"(a[1]), "r"(a[2]), "r"(a[3]), "r"(b[0]), "r"(b[1]));
}
__device__ __forceinline__ void mma_tf32(float* d, const uint32_t* a, const uint32_t* b) {
    asm volatile(
        "mma.sync.aligned.m16n8k8.row.col.f32.tf32.tf32.f32 "
        "{%0,%1,%2,%3}, {%4,%5,%6,%7}, {%8,%9}, {%0,%1,%2,%3};"
        : "+f"(d[0]), "+f"(d[1]), "+f"(d[2]), "+f"(d[3])
        : "r"(a[0]), "r"(a[1]), "r"(a[2]), "r"(a[3]), "r"(b[0]), "r"(b[1]));
}
__device__ __forceinline__ float tf32_rna(float v) {
    uint32_t o;
    asm("cvt.rna.tf32.f32 %0, %1;" : "=r"(o) : "f"(v));
    return __uint_as_float(o);
}

// ---------------------------------------------------------------------------
// Splits
// ---------------------------------------------------------------------------
__global__ void split_bf16(const float* __restrict__ src,
                           __nv_bfloat16* __restrict__ hi,
                           __nv_bfloat16* __restrict__ lo, int n) {
    int i = blockIdx.x * 256 + threadIdx.x;
    if (i < n) {
        float v = src[i];
        __nv_bfloat16 h = __float2bfloat16(v);
        hi[i] = h;
        lo[i] = __float2bfloat16(v - __bfloat162float(h));
    }
}
__global__ void split_tf32(const float* __restrict__ src,
                           float* __restrict__ hi, float* __restrict__ lo, int n) {
    int i = blockIdx.x * 256 + threadIdx.x;
    if (i < n) {
        float v = src[i];
        float h = tf32_rna(v);
        hi[i] = h;
        lo[i] = tf32_rna(v - h);
    }
}

// ---------------------------------------------------------------------------
// Transpose + tf32-split x: [b][c][n] fp32 -> xT_hi/lo [b][n][c]
// ---------------------------------------------------------------------------
__global__ __launch_bounds__(256) void transpose_split_x(
    const float* __restrict__ x, float* __restrict__ xhi, float* __restrict__ xlo) {
    const int b = blockIdx.z;
    const int c0 = blockIdx.y * 64;
    const int n0 = blockIdx.x * 32;
    __shared__ float s[64][33];
    const int tid = threadIdx.x;
#pragma unroll
    for (int i = 0; i < 8; i++) {
        int u = tid + 256 * i;
        int cc = u >> 5, nn = u & 31;
        s[cc][nn] = x[((size_t)b * CIN + c0 + cc) * HWN + n0 + nn];
    }
    __syncthreads();
#pragma unroll
    for (int i = 0; i < 8; i++) {
        int u = tid + 256 * i;
        int cc = u & 63, nn = u >> 6;
        float v = s[cc][nn];
        float h = tf32_rna(v);
        size_t idx = ((size_t)b * HWN + n0 + nn) * CIN + c0 + cc;
        xhi[idx] = h;
        xlo[idx] = tf32_rna(v - h);
    }
}

// ---------------------------------------------------------------------------
// tf32 3-term split GEMM via mma.sync.m16n8k8 (R5 hardware-proven version):
//   C[b][m][n] = sum_k A[m][k]*B[b][n][k]   (terms hh + hl + lh)
// CTA 128x128, BK=16, 8 warps (2x4), warp 64x32 (4x4 m16n8 tiles).
// ---------------------------------------------------------------------------
#define TLDS 20   // smem row stride in floats (16 + 4 pad)

__global__ __launch_bounds__(256, 2) void gemm_tf32(
    const float* __restrict__ Ahi, const float* __restrict__ Alo,
    const float* __restrict__ Bhi, const float* __restrict__ Blo,
    float* __restrict__ Cg, int M, int K) {
    __shared__ float As_hi[128 * TLDS];
    __shared__ float As_lo[128 * TLDS];
    __shared__ float Bs_hi[128 * TLDS];
    __shared__ float Bs_lo[128 * TLDS];

    const int tid = threadIdx.x;
    const int wid = tid >> 5;
    const int lane = tid & 31;

    const int b = blockIdx.z;
    const int m0 = blockIdx.y * 128;
    const int n0 = blockIdx.x * 128;

    const float* Bh = Bhi + (size_t)b * HWN * K;
    const float* Bl = Blo + (size_t)b * HWN * K;

    const int wm = (wid >> 2) * 64;
    const int wn = (wid & 3) * 32;

    const int qr = lane >> 2;    // 0..7
    const int qc = lane & 3;     // 0..3

    float acc[4][4][4];
#pragma unroll
    for (int mt = 0; mt < 4; mt++)
#pragma unroll
        for (int nt = 0; nt < 4; nt++)
#pragma unroll
            for (int r = 0; r < 4; r++) acc[mt][nt][r] = 0.f;

    for (int kc = 0; kc < K; kc += 16) {
        // load tiles (128 rows x 16 floats, hi+lo, A and B)
#pragma unroll
        for (int i = 0; i < 2; i++) {
            int u = tid + 256 * i;      // 0..511
            int row = u >> 2;
            int c4 = (u & 3) << 2;      // 0,4,8,12
            size_t sa = (size_t)(m0 + row) * K + kc + c4;
            *(float4*)&As_hi[row * TLDS + c4] = *(const float4*)(Ahi + sa);
            *(float4*)&As_lo[row * TLDS + c4] = *(const float4*)(Alo + sa);
            size_t sb = (size_t)(n0 + row) * K + kc + c4;
            *(float4*)&Bs_hi[row * TLDS + c4] = *(const float4*)(Bh + sb);
            *(float4*)&Bs_lo[row * TLDS + c4] = *(const float4*)(Bl + sb);
        }
        __syncthreads();

#pragma unroll
        for (int kk = 0; kk < 16; kk += 8) {
            // B fragments for all 4 n-tiles (hi and lo)
            uint32_t bh[4][2], bl[4][2];
#pragma unroll
            for (int nt = 0; nt < 4; nt++) {
                int nbase = (wn + nt * 8 + qr) * TLDS + kk + qc;
                bh[nt][0] = __float_as_uint(Bs_hi[nbase]);
                bh[nt][1] = __float_as_uint(Bs_hi[nbase + 4]);
                bl[nt][0] = __float_as_uint(Bs_lo[nbase]);
                bl[nt][1] = __float_as_uint(Bs_lo[nbase + 4]);
            }
#pragma unroll
            for (int mt = 0; mt < 4; mt++) {
                int abase = (wm + mt * 16 + qr) * TLDS + kk + qc;
                uint32_t ah[4], al[4];
                ah[0] = __float_as_uint(As_hi[abase]);
                ah[1] = __float_as_uint(As_hi[abase + 8 * TLDS]);
                ah[2] = __float_as_uint(As_hi[abase + 4]);
                ah[3] = __float_as_uint(As_hi[abase + 8 * TLDS + 4]);
                al[0] = __float_as_uint(As_lo[abase]);
                al[1] = __float_as_uint(As_lo[abase + 8 * TLDS]);
                al[2] = __float_as_uint(As_lo[abase + 4]);
                al[3] = __float_as_uint(As_lo[abase + 8 * TLDS + 4]);
#pragma unroll
                for (int nt = 0; nt < 4; nt++) {
                    mma_tf32(acc[mt][nt], ah, bh[nt]);   // hh
                    mma_tf32(acc[mt][nt], ah, bl[nt]);   // hl
                    mma_tf32(acc[mt][nt], al, bh[nt]);   // lh
                }
            }
        }
        __syncthreads();
    }

    // epilogue (m16n8 C layout)
#pragma unroll
    for (int mt = 0; mt < 4; mt++) {
        const int row0 = m0 + wm + mt * 16 + qr;
        const int row1 = row0 + 8;
        float* c0p = Cg + ((size_t)b * M + row0) * HWN + n0 + wn;
        float* c1p = Cg + ((size_t)b * M + row1) * HWN + n0 + wn;
        const int coff = qc << 1;
#pragma unroll
        for (int nt = 0; nt < 4; nt++) {
            *(float2*)(c0p + nt * 8 + coff) = make_float2(acc[mt][nt][0], acc[mt][nt][1]);
            *(float2*)(c1p + nt * 8 + coff) = make_float2(acc[mt][nt][2], acc[mt][nt][3]);
        }
    }
}

// ---------------------------------------------------------------------------
// bf16 3-term split GEMM (proj only) — R5 proven version
// ---------------------------------------------------------------------------
#define BK  32
#define LDS 40

__global__ __launch_bounds__(256, 2) void gemm_mma(
    const __nv_bfloat16* __restrict__ Ahi, const __nv_bfloat16* __restrict__ Alo,
    const __nv_bfloat16* __restrict__ Bhi, const __nv_bfloat16* __restrict__ Blo,
    float* __restrict__ Cg, int M, int K,
    const float* __restrict__ gamma, const float* __restrict__ beta,
    const float* __restrict__ mean, const float* __restrict__ var) {
    __shared__ __nv_bfloat16 As_hi[128 * LDS];
    __shared__ __nv_bfloat16 As_lo[128 * LDS];
    __shared__ __nv_bfloat16 Bs_hi[128 * LDS];
    __shared__ __nv_bfloat16 Bs_lo[128 * LDS];

    const int tid = threadIdx.x;
    const int wid = tid >> 5;
    const int lane = tid & 31;

    const int b = blockIdx.z;
    const int m0 = blockIdx.y * 128;
    const int n0 = blockIdx.x * 128;

    const __nv_bfloat16* Bh = Bhi + (size_t)b * HWN * K;
    const __nv_bfloat16* Bl = Blo + (size_t)b * HWN * K;

    const int wm = (wid >> 2) * 64;
    const int wn = (wid & 3) * 32;

    const int ar = lane & 15, ac = (lane >> 4) << 3;
    const int br = lane & 7,  bc = ((lane >> 3) & 1) << 3;

    float acc[4][4][4];
#pragma unroll
    for (int mt = 0; mt < 4; mt++)
#pragma unroll
        for (int nt = 0; nt < 4; nt++)
#pragma unroll
            for (int r = 0; r < 4; r++) acc[mt][nt][r] = 0.f;

    for (int kc = 0; kc < K; kc += BK) {
#pragma unroll
        for (int i = 0; i < 2; i++) {
            int u = tid + 256 * i;
            int row = u >> 2;
            int cu = (u & 3) << 3;
            size_t sa = (size_t)(m0 + row) * K + kc + cu;
            *(uint4*)&As_hi[row * LDS + cu] = *(const uint4*)(Ahi + sa);
            *(uint4*)&As_lo[row * LDS + cu] = *(const uint4*)(Alo + sa);
            size_t sb = (size_t)(n0 + row) * K + kc + cu;
            *(uint4*)&Bs_hi[row * LDS + cu] = *(const uint4*)(Bh + sb);
            *(uint4*)&Bs_lo[row * LDS + cu] = *(const uint4*)(Bl + sb);
        }
        __syncthreads();

#pragma unroll
        for (int kk = 0; kk < BK; kk += 16) {
            uint32_t ah[4][4], bhf[4][2];
#pragma unroll
            for (int mt = 0; mt < 4; mt++)
                ldmx4(ah[mt], smem_u32(&As_hi[(wm + mt * 16 + ar) * LDS + kk + ac]));
#pragma unroll
            for (int nt = 0; nt < 4; nt++)
                ldmx2(bhf[nt], smem_u32(&Bs_hi[(wn + nt * 8 + br) * LDS + kk + bc]));
#pragma unroll
            for (int mt = 0; mt < 4; mt++)
#pragma unroll
                for (int nt = 0; nt < 4; nt++)
                    mma_bf16(acc[mt][nt], ah[mt], bhf[nt]);

            uint32_t al[4][4];
#pragma unroll
            for (int mt = 0; mt < 4; mt++)
                ldmx4(al[mt], smem_u32(&As_lo[(wm + mt * 16 + ar) * LDS + kk + ac]));
#pragma unroll
            for (int mt = 0; mt < 4; mt++)
#pragma unroll
                for (int nt = 0; nt < 4; nt++)
                    mma_bf16(acc[mt][nt], al[mt], bhf[nt]);

            uint32_t blf[4][2];
#pragma unroll
            for (int nt = 0; nt < 4; nt++)
                ldmx2(blf[nt], smem_u32(&Bs_lo[(wn + nt * 8 + br) * LDS + kk + bc]));
#pragma unroll
            for (int mt = 0; mt < 4; mt++)
#pragma unroll
                for (int nt = 0; nt < 4; nt++)
                    mma_bf16(acc[mt][nt], ah[mt], blf[nt]);
        }
        __syncthreads();
    }

#pragma unroll
    for (int mt = 0; mt < 4; mt++) {
        const int row0 = m0 + wm + mt * 16 + (lane >> 2);
        const int row1 = row0 + 8;
        float s0 = 1.f, o0 = 0.f, s1 = 1.f, o1 = 0.f;
        if (gamma) {
            float iv0 = gamma[row0] * rsqrtf(var[row0] + 1e-5f);
            s0 = iv0; o0 = beta[row0] - mean[row0] * iv0;
            float iv1 = gamma[row1] * rsqrtf(var[row1] + 1e-5f);
            s1 = iv1; o1 = beta[row1] - mean[row1] * iv1;
        }
        float* c0p = Cg + ((size_t)b * M + row0) * HWN + n0 + wn;
        float* c1p = Cg + ((size_t)b * M + row1) * HWN + n0 + wn;
        const int coff = ((lane & 3) << 1);
#pragma unroll
        for (int nt = 0; nt < 4; nt++) {
            float2 v0, v1;
            v0.x = acc[mt][nt][0] * s0 + o0;
            v0.y = acc[mt][nt][1] * s0 + o0;
            v1.x = acc[mt][nt][2] * s1 + o1;
            v1.y = acc[mt][nt][3] * s1 + o1;
            *(float2*)(c0p + nt * 8 + coff) = v0;
            *(float2*)(c1p + nt * 8 + coff) = v1;
        }
    }
}

// ---------------------------------------------------------------------------
// FUSED depthwise 5x5 (pad 2) + grouped 1x1 (8-ch groups).
// Block = (tile 32x32, group g, batch b). Thread = 1 column x 4-row strip.
// FIX (R8): wd weight load previously required tids 64..263 in a 256-thread
// block, leaving wd[7][17..24] uninitialized. Now wd uses tid<200, wp tid<64.
// ---------------------------------------------------------------------------
__global__ __launch_bounds__(256) void dwpw(
    const float* __restrict__ qkv, const float* __restrict__ w_dw,
    const float* __restrict__ w_pw, float* __restrict__ agg) {
    const int tile = blockIdx.x;           // 0..3
    const int g = blockIdx.y;              // 0..95
    const int b = blockIdx.z;
    const int ty = (tile >> 1) * 32;
    const int tx = (tile & 1) * 32;

    __shared__ float h[8][36 * 36];
    __shared__ float wd[8][25];
    __shared__ float wp[64];

    const int tid = threadIdx.x;
    if (tid < 64) wp[tid] = w_pw[g * 64 + tid];
    if (tid < 200) {
        int c = tid / 25, t = tid % 25;
        wd[c][t] = w_dw[(g * 8 + c) * 25 + t];
    }

    const float* ip = qkv + ((size_t)b * C3 + (size_t)g * 8) * HWN;
    for (int idx = tid; idx < 8 * 1296; idx += 256) {
        int c = idx / 1296, rem = idx - c * 1296;
        int hy = rem / 36, hx = rem - hy * 36;
        int gy = ty + hy - 2, gx = tx + hx - 2;
        float v = 0.f;
        if ((unsigned)gy < 64u && (unsigned)gx < 64u) v = ip[(size_t)c * HWN + gy * 64 + gx];
        h[c][rem] = v;
    }
    __syncthreads();

    const int lx = tid & 31;          // column
    const int sy = (tid >> 5) << 2;   // strip row base (0,4,...,28)

    float d[8][4];
#pragma unroll
    for (int c = 0; c < 8; c++) {
        float a0 = 0.f, a1 = 0.f, a2 = 0.f, a3 = 0.f;
#pragma unroll
        for (int r = 0; r < 8; r++) {
            const float* hp = &h[c][(sy + r) * 36 + lx];
            float v0 = hp[0], v1 = hp[1], v2 = hp[2], v3 = hp[3], v4 = hp[4];
#pragma unroll
            for (int j = 0; j < 4; j++) {
                int dy = r - j;
                if (dy >= 0 && dy < 5) {
                    float s = v0 * wd[c][dy * 5 + 0];
                    s = fmaf(v1, wd[c][dy * 5 + 1], s);
                    s = fmaf(v2, wd[c][dy * 5 + 2], s);
                    s = fmaf(v3, wd[c][dy * 5 + 3], s);
                    s = fmaf(v4, wd[c][dy * 5 + 4], s);
                    if (j == 0) a0 += s;
                    else if (j == 1) a1 += s;
                    else if (j == 2) a2 += s;
                    else a3 += s;
                }
            }
        }
        d[c][0] = a0; d[c][1] = a1; d[c][2] = a2; d[c][3] = a3;
    }

    float* op = agg + ((size_t)b * C3 + (size_t)g * 8) * HWN;
#pragma unroll
    for (int j = 0; j < 4; j++) {
        size_t pbase = (size_t)(ty + sy + j) * 64 + tx + lx;
#pragma unroll
        for (int o = 0; o < 8; o++) {
            float s = 0.f;
#pragma unroll
            for (int c = 0; c < 8; c++) s = fmaf(wp[o * 8 + c], d[c][j], s);
            op[(size_t)o * HWN + pbase] = s;
        }
    }
}

// ---------------------------------------------------------------------------
// ReLU linear attention. Pass 1: warp w owns k-channel d=w (kv row in regs,
// shuffle-reduced, no atomics). Pass 2: float4 q loads, bf16 hi/lo transposed
// output (proj B operand).
// ---------------------------------------------------------------------------
__global__ __launch_bounds__(256) void relu_lin_att(
    const float* __restrict__ qkv, const float* __restrict__ agg,
    __nv_bfloat16* __restrict__ ohi, __nv_bfloat16* __restrict__ olo) {
    const int bg = blockIdx.x;
    const int b = bg >> 6;
    const int g = bg & 63;
    const float* base = (g < 32)
        ? qkv + ((size_t)b * C3 + (size_t)g * 24) * HWN
        : agg + ((size_t)b * C3 + (size_t)(g - 32) * 24) * HWN;

    __shared__ float kvs[72];
    const int tid = threadIdx.x;
    const int w = tid >> 5;        // warp = k-channel d
    const int lane = tid & 31;

    // Pass 1: kv[w][e] = sum_n relu(k_w) * v_e ; kv[w][8] = sum_n relu(k_w)
    float kvr[9];
#pragma unroll
    for (int i = 0; i < 9; i++) kvr[i] = 0.f;

    const float* kch = base + (size_t)(8 + w) * HWN;
    for (int n4 = lane * 4; n4 < HWN; n4 += 128) {
        float4 kk = *(const float4*)(kch + n4);
        kk.x = fmaxf(kk.x, 0.f); kk.y = fmaxf(kk.y, 0.f);
        kk.z = fmaxf(kk.z, 0.f); kk.w = fmaxf(kk.w, 0.f);
#pragma unroll
        for (int e = 0; e < 8; e++) {
            float4 vv = *(const float4*)(base + (size_t)(16 + e) * HWN + n4);
            kvr[e] = fmaf(kk.x, vv.x, kvr[e]);
            kvr[e] = fmaf(kk.y, vv.y, kvr[e]);
            kvr[e] = fmaf(kk.z, vv.z, kvr[e]);
            kvr[e] = fmaf(kk.w, vv.w, kvr[e]);
        }
        kvr[8] += kk.x + kk.y + kk.z + kk.w;
    }
#pragma unroll
    for (int i = 0; i < 9; i++) {
        float v = kvr[i];
        v += __shfl_xor_sync(0xffffffffu, v, 16);
        v += __shfl_xor_sync(0xffffffffu, v, 8);
        v += __shfl_xor_sync(0xffffffffu, v, 4);
        v += __shfl_xor_sync(0xffffffffu, v, 2);
        v += __shfl_xor_sync(0xffffffffu, v, 1);
        if (lane == 0) kvs[w * 9 + i] = v;
    }
    __syncthreads();

    // Pass 2
    for (int n4 = tid * 4; n4 < HWN; n4 += 1024) {
        float4 q4[8];
#pragma unroll
        for (int d0 = 0; d0 < 8; d0++) {
            float4 q = *(const float4*)(base + (size_t)d0 * HWN + n4);
            q.x = fmaxf(q.x, 0.f); q.y = fmaxf(q.y, 0.f);
            q.z = fmaxf(q.z, 0.f); q.w = fmaxf(q.w, 0.f);
            q4[d0] = q;
        }
#pragma unroll
        for (int px = 0; px < 4; px++) {
            float qd[8];
#pragma unroll
            for (int d0 = 0; d0 < 8; d0++)
                qd[d0] = px == 0 ? q4[d0].x : px == 1 ? q4[d0].y : px == 2 ? q4[d0].z : q4[d0].w;
            float den = 0.f;
#pragma unroll
            for (int d0 = 0; d0 < 8; d0++) den = fmaf(qd[d0], kvs[d0 * 9 + 8], den);
            float rden = 1.f / (den + 1e-15f);
            __align__(16) __nv_bfloat16 hi[8], lo[8];
#pragma unroll
            for (int e = 0; e < 8; e++) {
                float num = 0.f;
#pragma unroll
                for (int d0 = 0; d0 < 8; d0++) num = fmaf(qd[d0], kvs[d0 * 9 + e], num);
                float v = num * rden;
                __nv_bfloat16 hh = __float2bfloat16(v);
                hi[e] = hh;
                lo[e] = __float2bfloat16(v - __bfloat162float(hh));
            }
            size_t idx = ((size_t)b * HWN + n4 + px) * CATT + g * 8;
            *(uint4*)(ohi + idx) = *(const uint4*)hi;
            *(uint4*)(olo + idx) = *(const uint4*)lo;
        }
    }
}

// ---------------------------------------------------------------------------
// Launch
// ---------------------------------------------------------------------------
extern "C" void kernel_launch(void* const* d_in, const int* in_sizes, int n_in,
                              void* d_out, int out_size) {
    const float* x      = (const float*)d_in[0];
    const float* w_qkv  = (const float*)d_in[1];
    const float* w_dw   = (const float*)d_in[2];
    const float* w_pw   = (const float*)d_in[3];
    const float* w_proj = (const float*)d_in[4];
    const float* gamma  = (const float*)d_in[5];
    const float* beta   = (const float*)d_in[6];
    const float* mean   = (const float*)d_in[7];
    const float* var    = (const float*)d_in[8];
    float* out = (float*)d_out;

    float *qkv_s, *agg_s, *xh, *xl, *wqh, *wql;
    __nv_bfloat16 *ah, *al, *wph, *wpl;
    cudaGetSymbolAddress((void**)&qkv_s, g_qkv);
    cudaGetSymbolAddress((void**)&agg_s, g_agg);
    cudaGetSymbolAddress((void**)&xh, g_xT_hi);
    cudaGetSymbolAddress((void**)&xl, g_xT_lo);
    cudaGetSymbolAddress((void**)&ah, g_attT_hi);
    cudaGetSymbolAddress((void**)&al, g_attT_lo);
    cudaGetSymbolAddress((void**)&wqh, g_wqkv_hi);
    cudaGetSymbolAddress((void**)&wql, g_wqkv_lo);
    cudaGetSymbolAddress((void**)&wph, g_wproj_hi);
    cudaGetSymbolAddress((void**)&wpl, g_wproj_lo);

    // 0) weight splits + x transpose/split
    split_tf32<<<(C3 * CIN + 255) / 256, 256>>>(w_qkv, wqh, wql, C3 * CIN);
    split_bf16<<<(256 * CATT + 255) / 256, 256>>>(w_proj, wph, wpl, 256 * CATT);
    {
        dim3 grid(HWN / 32, CIN / 64, BATCH);
        transpose_split_x<<<grid, 256>>>(x, xh, xl);
    }

    // 1) qkv GEMM (tf32 split): M=768, K=256
    {
        dim3 grid(HWN / 128, C3 / 128, BATCH);   // (32, 6, 16)
        gemm_tf32<<<grid, 256>>>(wqh, wql, xh, xl, qkv_s, C3, CIN);
    }

    // 2+3) fused depthwise 5x5 + grouped pointwise -> agg
    {
        dim3 grid(4, PWG, BATCH);                // (4, 96, 16)
        dwpw<<<grid, 256>>>(qkv_s, w_dw, w_pw, agg_s);
    }

    // 4) attention -> transposed bf16 hi/lo
    relu_lin_att<<<BATCH * 64, 256>>>(qkv_s, agg_s, ah, al);

    // 5) proj GEMM (bf16 split) + BN: M=256, K=512
    {
        dim3 grid(HWN / 128, 256 / 128, BATCH);  // (32, 2, 16)
        gemm_mma<<<grid, 256>>>(wph, wpl, ah, al, out, 256, CATT,
                                gamma, beta, mean, var);
    }
}

// round 9
// speedup vs baseline: 1.4238x; 1.0175x over previous
#include <cuda_runtime.h>
#include <cuda_bf16.h>
#include <cstdint>

// Problem constants
#define BATCH 16
#define CIN   256
#define HWN   4096          // 64*64
#define C3    768           // 3*TOTAL
#define CATT  512           // 2*TOTAL
#define PWG   96

// ---------------------------------------------------------------------------
// Scratch (static device memory)
// ---------------------------------------------------------------------------
__device__ float g_qkv[BATCH * C3 * HWN];               // 201 MB
__device__ float g_agg[BATCH * C3 * HWN];               // 201 MB
__device__ float g_xT_hi[BATCH * HWN * CIN];            // 67 MB (tf32 bits)
__device__ float g_xT_lo[BATCH * HWN * CIN];            // 67 MB
__device__ __nv_bfloat16 g_attT_hi[BATCH * HWN * CATT]; // 67 MB
__device__ __nv_bfloat16 g_attT_lo[BATCH * HWN * CATT];
__device__ float g_wqkv_hi[C3 * CIN];
__device__ float g_wqkv_lo[C3 * CIN];
__device__ __nv_bfloat16 g_wproj_hi[256 * CATT];
__device__ __nv_bfloat16 g_wproj_lo[256 * CATT];

// ---------------------------------------------------------------------------
// Helpers
// ---------------------------------------------------------------------------
__device__ __forceinline__ uint32_t smem_u32(const void* p) {
    uint32_t a;
    asm("{ .reg .u64 t; cvta.to.shared.u64 t, %1; cvt.u32.u64 %0, t; }" : "=r"(a) : "l"(p));
    return a;
}
__device__ __forceinline__ void ldmx4(uint32_t* r, uint32_t addr) {
    asm volatile("ldmatrix.sync.aligned.m8n8.x4.shared.b16 {%0,%1,%2,%3}, [%4];"
                 : "=r"(r[0]), "=r"(r[1]), "=r"(r[2]), "=r"(r[3]) : "r"(addr));
}
__device__ __forceinline__ void ldmx2(uint32_t* r, uint32_t addr) {
    asm volatile("ldmatrix.sync.aligned.m8n8.x2.shared.b16 {%0,%1}, [%2];"
                 : "=r"(r[0]), "=r"(r[1]) : "r"(addr));
}
__device__ __forceinline__ void mma_bf16(float* d, const uint32_t* a, const uint32_t* b) {
    asm volatile(
        "mma.sync.aligned.m16n8k16.row.col.f32.bf16.bf16.f32 "
        "{%0,%1,%2,%3}, {%4,%5,%6,%7}, {%8,%9}, {%0,%1,%2,%3};"
        : "+f"(d[0]), "+f"(d[1]), "+f"(d[2]), "+f"(d[3])
        : "r"(a[0]), "r"(a[1]), "r"(a[2]), "r"(a[3]), "r"(b[0]), "r"(b[1]));
}
__device__ __forceinline__ void mma_tf32(float* d, const uint32_t* a, const uint32_t* b) {
    asm volatile(
        "mma.sync.aligned.m16n8k8.row.col.f32.tf32.tf32.f32 "
        "{%0,%1,%2,%3}, {%4,%5,%6,%7}, {%8,%9}, {%0,%1,%2,%3};"
        : "+f"(d[0]), "+f"(d[1]), "+f"(d[2]), "+f"(d[3])
        : "r"(a[0]), "r"(a[1]), "r"(a[2]), "r"(a[3]), "r"(b[0]), "r"(b[1]));
}
__device__ __forceinline__ float tf32_rna(float v) {
    uint32_t o;
    asm("cvt.rna.tf32.f32 %0, %1;" : "=r"(o) : "f"(v));
    return __uint_as_float(o);
}

// ---------------------------------------------------------------------------
// Splits
// ---------------------------------------------------------------------------
__global__ void split_bf16(const float* __restrict__ src,
                           __nv_bfloat16* __restrict__ hi,
                           __nv_bfloat16* __restrict__ lo, int n) {
    int i = blockIdx.x * 256 + threadIdx.x;
    if (i < n) {
        float v = src[i];
        __nv_bfloat16 h = __float2bfloat16(v);
        hi[i] = h;
        lo[i] = __float2bfloat16(v - __bfloat162float(h));
    }
}
__global__ void split_tf32(const float* __restrict__ src,
                           float* __restrict__ hi, float* __restrict__ lo, int n) {
    int i = blockIdx.x * 256 + threadIdx.x;
    if (i < n) {
        float v = src[i];
        float h = tf32_rna(v);
        hi[i] = h;
        lo[i] = tf32_rna(v - h);
    }
}

// ---------------------------------------------------------------------------
// Transpose + tf32-split x: [b][c][n] fp32 -> xT_hi/lo [b][n][c]
// ---------------------------------------------------------------------------
__global__ __launch_bounds__(256) void transpose_split_x(
    const float* __restrict__ x, float* __restrict__ xhi, float* __restrict__ xlo) {
    const int b = blockIdx.z;
    const int c0 = blockIdx.y * 64;
    const int n0 = blockIdx.x * 32;
    __shared__ float s[64][33];
    const int tid = threadIdx.x;
#pragma unroll
    for (int i = 0; i < 8; i++) {
        int u = tid + 256 * i;
        int cc = u >> 5, nn = u & 31;
        s[cc][nn] = x[((size_t)b * CIN + c0 + cc) * HWN + n0 + nn];
    }
    __syncthreads();
#pragma unroll
    for (int i = 0; i < 8; i++) {
        int u = tid + 256 * i;
        int cc = u & 63, nn = u >> 6;
        float v = s[cc][nn];
        float h = tf32_rna(v);
        size_t idx = ((size_t)b * HWN + n0 + nn) * CIN + c0 + cc;
        xhi[idx] = h;
        xlo[idx] = tf32_rna(v - h);
    }
}

// ---------------------------------------------------------------------------
// tf32 3-term split GEMM via mma.sync.m16n8k8.
//   C[b][m][n] = sum_k A[m][k]*B[b][n][k]   (terms hh + hl + lh)
// CTA 128x128, BK=16, 8 warps (2x4), warp 64x32 (4x4 m16n8 tiles).
// R9: fragment loads via ldmatrix.b16 on 32-bit data (CUTLASS tf32 path):
//   A: 1x LDSM.x4 per (mt, half) — quadrants {row,row+8}x{k,k+4}
//   B: 1x LDSM.x2 per (nt, half) — quadrants {k,k+4}
// TLDS=20 pad keeps all 8 row-addresses of each LDSM phase in distinct banks.
// ---------------------------------------------------------------------------
#define TLDS 20   // smem row stride in floats (16 + 4 pad)

__global__ __launch_bounds__(256, 2) void gemm_tf32(
    const float* __restrict__ Ahi, const float* __restrict__ Alo,
    const float* __restrict__ Bhi, const float* __restrict__ Blo,
    float* __restrict__ Cg, int M, int K) {
    __shared__ float As_hi[128 * TLDS];
    __shared__ float As_lo[128 * TLDS];
    __shared__ float Bs_hi[128 * TLDS];
    __shared__ float Bs_lo[128 * TLDS];

    const int tid = threadIdx.x;
    const int wid = tid >> 5;
    const int lane = tid & 31;

    const int b = blockIdx.z;
    const int m0 = blockIdx.y * 128;
    const int n0 = blockIdx.x * 128;

    const float* Bh = Bhi + (size_t)b * HWN * K;
    const float* Bl = Blo + (size_t)b * HWN * K;

    const int wm = (wid >> 2) * 64;
    const int wn = (wid & 3) * 32;

    const int qr = lane >> 2;    // 0..7
    const int qc = lane & 3;     // 0..3

    // ldmatrix per-lane source coordinates
    const int aro = (lane & 7) + ((lane >> 3) & 1) * 8;  // A row offset in 16-row tile
    const int aco = (lane >> 4) * 4;                     // A col offset (k quadrant)
    const int bro = lane & 7;                            // B row offset in 8-row tile
    const int bco = ((lane >> 3) & 1) * 4;               // B col offset (k quadrant)

    float acc[4][4][4];
#pragma unroll
    for (int mt = 0; mt < 4; mt++)
#pragma unroll
        for (int nt = 0; nt < 4; nt++)
#pragma unroll
            for (int r = 0; r < 4; r++) acc[mt][nt][r] = 0.f;

    for (int kc = 0; kc < K; kc += 16) {
        // load tiles (128 rows x 16 floats, hi+lo, A and B)
#pragma unroll
        for (int i = 0; i < 2; i++) {
            int u = tid + 256 * i;      // 0..511
            int row = u >> 2;
            int c4 = (u & 3) << 2;      // 0,4,8,12
            size_t sa = (size_t)(m0 + row) * K + kc + c4;
            *(float4*)&As_hi[row * TLDS + c4] = *(const float4*)(Ahi + sa);
            *(float4*)&As_lo[row * TLDS + c4] = *(const float4*)(Alo + sa);
            size_t sb = (size_t)(n0 + row) * K + kc + c4;
            *(float4*)&Bs_hi[row * TLDS + c4] = *(const float4*)(Bh + sb);
            *(float4*)&Bs_lo[row * TLDS + c4] = *(const float4*)(Bl + sb);
        }
        __syncthreads();

#pragma unroll
        for (int kk = 0; kk < 16; kk += 8) {
            // B fragments for all 4 n-tiles (hi and lo) via LDSM.x2
            uint32_t bh[4][2], bl[4][2];
#pragma unroll
            for (int nt = 0; nt < 4; nt++) {
                ldmx2(bh[nt], smem_u32(&Bs_hi[(wn + nt * 8 + bro) * TLDS + kk + bco]));
                ldmx2(bl[nt], smem_u32(&Bs_lo[(wn + nt * 8 + bro) * TLDS + kk + bco]));
            }
#pragma unroll
            for (int mt = 0; mt < 4; mt++) {
                uint32_t ah[4], al[4];
                ldmx4(ah, smem_u32(&As_hi[(wm + mt * 16 + aro) * TLDS + kk + aco]));
                ldmx4(al, smem_u32(&As_lo[(wm + mt * 16 + aro) * TLDS + kk + aco]));
#pragma unroll
                for (int nt = 0; nt < 4; nt++) {
                    mma_tf32(acc[mt][nt], ah, bh[nt]);   // hh
                    mma_tf32(acc[mt][nt], ah, bl[nt]);   // hl
                    mma_tf32(acc[mt][nt], al, bh[nt]);   // lh
                }
            }
        }
        __syncthreads();
    }

    // epilogue (m16n8 C layout)
#pragma unroll
    for (int mt = 0; mt < 4; mt++) {
        const int row0 = m0 + wm + mt * 16 + qr;
        const int row1 = row0 + 8;
        float* c0p = Cg + ((size_t)b * M + row0) * HWN + n0 + wn;
        float* c1p = Cg + ((size_t)b * M + row1) * HWN + n0 + wn;
        const int coff = qc << 1;
#pragma unroll
        for (int nt = 0; nt < 4; nt++) {
            *(float2*)(c0p + nt * 8 + coff) = make_float2(acc[mt][nt][0], acc[mt][nt][1]);
            *(float2*)(c1p + nt * 8 + coff) = make_float2(acc[mt][nt][2], acc[mt][nt][3]);
        }
    }
}

// ---------------------------------------------------------------------------
// bf16 3-term split GEMM (proj only) — proven version
// ---------------------------------------------------------------------------
#define BK  32
#define LDS 40

__global__ __launch_bounds__(256, 2) void gemm_mma(
    const __nv_bfloat16* __restrict__ Ahi, const __nv_bfloat16* __restrict__ Alo,
    const __nv_bfloat16* __restrict__ Bhi, const __nv_bfloat16* __restrict__ Blo,
    float* __restrict__ Cg, int M, int K,
    const float* __restrict__ gamma, const float* __restrict__ beta,
    const float* __restrict__ mean, const float* __restrict__ var) {
    __shared__ __nv_bfloat16 As_hi[128 * LDS];
    __shared__ __nv_bfloat16 As_lo[128 * LDS];
    __shared__ __nv_bfloat16 Bs_hi[128 * LDS];
    __shared__ __nv_bfloat16 Bs_lo[128 * LDS];

    const int tid = threadIdx.x;
    const int wid = tid >> 5;
    const int lane = tid & 31;

    const int b = blockIdx.z;
    const int m0 = blockIdx.y * 128;
    const int n0 = blockIdx.x * 128;

    const __nv_bfloat16* Bh = Bhi + (size_t)b * HWN * K;
    const __nv_bfloat16* Bl = Blo + (size_t)b * HWN * K;

    const int wm = (wid >> 2) * 64;
    const int wn = (wid & 3) * 32;

    const int ar = lane & 15, ac = (lane >> 4) << 3;
    const int br = lane & 7,  bc = ((lane >> 3) & 1) << 3;

    float acc[4][4][4];
#pragma unroll
    for (int mt = 0; mt < 4; mt++)
#pragma unroll
        for (int nt = 0; nt < 4; nt++)
#pragma unroll
            for (int r = 0; r < 4; r++) acc[mt][nt][r] = 0.f;

    for (int kc = 0; kc < K; kc += BK) {
#pragma unroll
        for (int i = 0; i < 2; i++) {
            int u = tid + 256 * i;
            int row = u >> 2;
            int cu = (u & 3) << 3;
            size_t sa = (size_t)(m0 + row) * K + kc + cu;
            *(uint4*)&As_hi[row * LDS + cu] = *(const uint4*)(Ahi + sa);
            *(uint4*)&As_lo[row * LDS + cu] = *(const uint4*)(Alo + sa);
            size_t sb = (size_t)(n0 + row) * K + kc + cu;
            *(uint4*)&Bs_hi[row * LDS + cu] = *(const uint4*)(Bh + sb);
            *(uint4*)&Bs_lo[row * LDS + cu] = *(const uint4*)(Bl + sb);
        }
        __syncthreads();

#pragma unroll
        for (int kk = 0; kk < BK; kk += 16) {
            uint32_t ah[4][4], bhf[4][2];
#pragma unroll
            for (int mt = 0; mt < 4; mt++)
                ldmx4(ah[mt], smem_u32(&As_hi[(wm + mt * 16 + ar) * LDS + kk + ac]));
#pragma unroll
            for (int nt = 0; nt < 4; nt++)
                ldmx2(bhf[nt], smem_u32(&Bs_hi[(wn + nt * 8 + br) * LDS + kk + bc]));
#pragma unroll
            for (int mt = 0; mt < 4; mt++)
#pragma unroll
                for (int nt = 0; nt < 4; nt++)
                    mma_bf16(acc[mt][nt], ah[mt], bhf[nt]);

            uint32_t al[4][4];
#pragma unroll
            for (int mt = 0; mt < 4; mt++)
                ldmx4(al[mt], smem_u32(&As_lo[(wm + mt * 16 + ar) * LDS + kk + ac]));
#pragma unroll
            for (int mt = 0; mt < 4; mt++)
#pragma unroll
                for (int nt = 0; nt < 4; nt++)
                    mma_bf16(acc[mt][nt], al[mt], bhf[nt]);

            uint32_t blf[4][2];
#pragma unroll
            for (int nt = 0; nt < 4; nt++)
                ldmx2(blf[nt], smem_u32(&Bs_lo[(wn + nt * 8 + br) * LDS + kk + bc]));
#pragma unroll
            for (int mt = 0; mt < 4; mt++)
#pragma unroll
                for (int nt = 0; nt < 4; nt++)
                    mma_bf16(acc[mt][nt], ah[mt], blf[nt]);
        }
        __syncthreads();
    }

#pragma unroll
    for (int mt = 0; mt < 4; mt++) {
        const int row0 = m0 + wm + mt * 16 + (lane >> 2);
        const int row1 = row0 + 8;
        float s0 = 1.f, o0 = 0.f, s1 = 1.f, o1 = 0.f;
        if (gamma) {
            float iv0 = gamma[row0] * rsqrtf(var[row0] + 1e-5f);
            s0 = iv0; o0 = beta[row0] - mean[row0] * iv0;
            float iv1 = gamma[row1] * rsqrtf(var[row1] + 1e-5f);
            s1 = iv1; o1 = beta[row1] - mean[row1] * iv1;
        }
        float* c0p = Cg + ((size_t)b * M + row0) * HWN + n0 + wn;
        float* c1p = Cg + ((size_t)b * M + row1) * HWN + n0 + wn;
        const int coff = ((lane & 3) << 1);
#pragma unroll
        for (int nt = 0; nt < 4; nt++) {
            float2 v0, v1;
            v0.x = acc[mt][nt][0] * s0 + o0;
            v0.y = acc[mt][nt][1] * s0 + o0;
            v1.x = acc[mt][nt][2] * s1 + o1;
            v1.y = acc[mt][nt][3] * s1 + o1;
            *(float2*)(c0p + nt * 8 + coff) = v0;
            *(float2*)(c1p + nt * 8 + coff) = v1;
        }
    }
}

// ---------------------------------------------------------------------------
// FUSED depthwise 5x5 (pad 2) + grouped 1x1 (8-ch groups).
// Block = (tile 32x32, group g, batch b). Thread = 1 column x 4-row strip.
// ---------------------------------------------------------------------------
__global__ __launch_bounds__(256) void dwpw(
    const float* __restrict__ qkv, const float* __restrict__ w_dw,
    const float* __restrict__ w_pw, float* __restrict__ agg) {
    const int tile = blockIdx.x;           // 0..3
    const int g = blockIdx.y;              // 0..95
    const int b = blockIdx.z;
    const int ty = (tile >> 1) * 32;
    const int tx = (tile & 1) * 32;

    __shared__ float h[8][36 * 36];
    __shared__ float wd[8][25];
    __shared__ float wp[64];

    const int tid = threadIdx.x;
    if (tid < 64) wp[tid] = w_pw[g * 64 + tid];
    if (tid < 200) {
        int c = tid / 25, t = tid % 25;
        wd[c][t] = w_dw[(g * 8 + c) * 25 + t];
    }

    const float* ip = qkv + ((size_t)b * C3 + (size_t)g * 8) * HWN;
    for (int idx = tid; idx < 8 * 1296; idx += 256) {
        int c = idx / 1296, rem = idx - c * 1296;
        int hy = rem / 36, hx = rem - hy * 36;
        int gy = ty + hy - 2, gx = tx + hx - 2;
        float v = 0.f;
        if ((unsigned)gy < 64u && (unsigned)gx < 64u) v = ip[(size_t)c * HWN + gy * 64 + gx];
        h[c][rem] = v;
    }
    __syncthreads();

    const int lx = tid & 31;          // column
    const int sy = (tid >> 5) << 2;   // strip row base (0,4,...,28)

    float d[8][4];
#pragma unroll
    for (int c = 0; c < 8; c++) {
        float a0 = 0.f, a1 = 0.f, a2 = 0.f, a3 = 0.f;
#pragma unroll
        for (int r = 0; r < 8; r++) {
            const float* hp = &h[c][(sy + r) * 36 + lx];
            float v0 = hp[0], v1 = hp[1], v2 = hp[2], v3 = hp[3], v4 = hp[4];
#pragma unroll
            for (int j = 0; j < 4; j++) {
                int dy = r - j;
                if (dy >= 0 && dy < 5) {
                    float s = v0 * wd[c][dy * 5 + 0];
                    s = fmaf(v1, wd[c][dy * 5 + 1], s);
                    s = fmaf(v2, wd[c][dy * 5 + 2], s);
                    s = fmaf(v3, wd[c][dy * 5 + 3], s);
                    s = fmaf(v4, wd[c][dy * 5 + 4], s);
                    if (j == 0) a0 += s;
                    else if (j == 1) a1 += s;
                    else if (j == 2) a2 += s;
                    else a3 += s;
                }
            }
        }
        d[c][0] = a0; d[c][1] = a1; d[c][2] = a2; d[c][3] = a3;
    }

    float* op = agg + ((size_t)b * C3 + (size_t)g * 8) * HWN;
#pragma unroll
    for (int j = 0; j < 4; j++) {
        size_t pbase = (size_t)(ty + sy + j) * 64 + tx + lx;
#pragma unroll
        for (int o = 0; o < 8; o++) {
            float s = 0.f;
#pragma unroll
            for (int c = 0; c < 8; c++) s = fmaf(wp[o * 8 + c], d[c][j], s);
            op[(size_t)o * HWN + pbase] = s;
        }
    }
}

// ---------------------------------------------------------------------------
// ReLU linear attention. Pass 1: warp w owns k-channel d=w (kv row in regs,
// shuffle-reduced, no atomics). Pass 2: float4 q loads, bf16 hi/lo transposed
// output (proj B operand).
// ---------------------------------------------------------------------------
__global__ __launch_bounds__(256) void relu_lin_att(
    const float* __restrict__ qkv, const float* __restrict__ agg,
    __nv_bfloat16* __restrict__ ohi, __nv_bfloat16* __restrict__ olo) {
    const int bg = blockIdx.x;
    const int b = bg >> 6;
    const int g = bg & 63;
    const float* base = (g < 32)
        ? qkv + ((size_t)b * C3 + (size_t)g * 24) * HWN
        : agg + ((size_t)b * C3 + (size_t)(g - 32) * 24) * HWN;

    __shared__ float kvs[72];
    const int tid = threadIdx.x;
    const int w = tid >> 5;        // warp = k-channel d
    const int lane = tid & 31;

    // Pass 1: kv[w][e] = sum_n relu(k_w) * v_e ; kv[w][8] = sum_n relu(k_w)
    float kvr[9];
#pragma unroll
    for (int i = 0; i < 9; i++) kvr[i] = 0.f;

    const float* kch = base + (size_t)(8 + w) * HWN;
    for (int n4 = lane * 4; n4 < HWN; n4 += 128) {
        float4 kk = *(const float4*)(kch + n4);
        kk.x = fmaxf(kk.x, 0.f); kk.y = fmaxf(kk.y, 0.f);
        kk.z = fmaxf(kk.z, 0.f); kk.w = fmaxf(kk.w, 0.f);
#pragma unroll
        for (int e = 0; e < 8; e++) {
            float4 vv = *(const float4*)(base + (size_t)(16 + e) * HWN + n4);
            kvr[e] = fmaf(kk.x, vv.x, kvr[e]);
            kvr[e] = fmaf(kk.y, vv.y, kvr[e]);
            kvr[e] = fmaf(kk.z, vv.z, kvr[e]);
            kvr[e] = fmaf(kk.w, vv.w, kvr[e]);
        }
        kvr[8] += kk.x + kk.y + kk.z + kk.w;
    }
#pragma unroll
    for (int i = 0; i < 9; i++) {
        float v = kvr[i];
        v += __shfl_xor_sync(0xffffffffu, v, 16);
        v += __shfl_xor_sync(0xffffffffu, v, 8);
        v += __shfl_xor_sync(0xffffffffu, v, 4);
        v += __shfl_xor_sync(0xffffffffu, v, 2);
        v += __shfl_xor_sync(0xffffffffu, v, 1);
        if (lane == 0) kvs[w * 9 + i] = v;
    }
    __syncthreads();

    // Pass 2
    for (int n4 = tid * 4; n4 < HWN; n4 += 1024) {
        float4 q4[8];
#pragma unroll
        for (int d0 = 0; d0 < 8; d0++) {
            float4 q = *(const float4*)(base + (size_t)d0 * HWN + n4);
            q.x = fmaxf(q.x, 0.f); q.y = fmaxf(q.y, 0.f);
            q.z = fmaxf(q.z, 0.f); q.w = fmaxf(q.w, 0.f);
            q4[d0] = q;
        }
#pragma unroll
        for (int px = 0; px < 4; px++) {
            float qd[8];
#pragma unroll
            for (int d0 = 0; d0 < 8; d0++)
                qd[d0] = px == 0 ? q4[d0].x : px == 1 ? q4[d0].y : px == 2 ? q4[d0].z : q4[d0].w;
            float den = 0.f;
#pragma unroll
            for (int d0 = 0; d0 < 8; d0++) den = fmaf(qd[d0], kvs[d0 * 9 + 8], den);
            float rden = 1.f / (den + 1e-15f);
            __align__(16) __nv_bfloat16 hi[8], lo[8];
#pragma unroll
            for (int e = 0; e < 8; e++) {
                float num = 0.f;
#pragma unroll
                for (int d0 = 0; d0 < 8; d0++) num = fmaf(qd[d0], kvs[d0 * 9 + e], num);
                float v = num * rden;
                __nv_bfloat16 hh = __float2bfloat16(v);
                hi[e] = hh;
                lo[e] = __float2bfloat16(v - __bfloat162float(hh));
            }
            size_t idx = ((size_t)b * HWN + n4 + px) * CATT + g * 8;
            *(uint4*)(ohi + idx) = *(const uint4*)hi;
            *(uint4*)(olo + idx) = *(const uint4*)lo;
        }
    }
}

// ---------------------------------------------------------------------------
// Launch
// ---------------------------------------------------------------------------
extern "C" void kernel_launch(void* const* d_in, const int* in_sizes, int n_in,
                              void* d_out, int out_size) {
    const float* x      = (const float*)d_in[0];
    const float* w_qkv  = (const float*)d_in[1];
    const float* w_dw   = (const float*)d_in[2];
    const float* w_pw   = (const float*)d_in[3];
    const float* w_proj = (const float*)d_in[4];
    const float* gamma  = (const float*)d_in[5];
    const float* beta   = (const float*)d_in[6];
    const float* mean   = (const float*)d_in[7];
    const float* var    = (const float*)d_in[8];
    float* out = (float*)d_out;

    float *qkv_s, *agg_s, *xh, *xl, *wqh, *wql;
    __nv_bfloat16 *ah, *al, *wph, *wpl;
    cudaGetSymbolAddress((void**)&qkv_s, g_qkv);
    cudaGetSymbolAddress((void**)&agg_s, g_agg);
    cudaGetSymbolAddress((void**)&xh, g_xT_hi);
    cudaGetSymbolAddress((void**)&xl, g_xT_lo);
    cudaGetSymbolAddress((void**)&ah, g_attT_hi);
    cudaGetSymbolAddress((void**)&al, g_attT_lo);
    cudaGetSymbolAddress((void**)&wqh, g_wqkv_hi);
    cudaGetSymbolAddress((void**)&wql, g_wqkv_lo);
    cudaGetSymbolAddress((void**)&wph, g_wproj_hi);
    cudaGetSymbolAddress((void**)&wpl, g_wproj_lo);

    // 0) weight splits + x transpose/split
    split_tf32<<<(C3 * CIN + 255) / 256, 256>>>(w_qkv, wqh, wql, C3 * CIN);
    split_bf16<<<(256 * CATT + 255) / 256, 256>>>(w_proj, wph, wpl, 256 * CATT);
    {
        dim3 grid(HWN / 32, CIN / 64, BATCH);
        transpose_split_x<<<grid, 256>>>(x, xh, xl);
    }

    // 1) qkv GEMM (tf32 split): M=768, K=256
    {
        dim3 grid(HWN / 128, C3 / 128, BATCH);   // (32, 6, 16)
        gemm_tf32<<<grid, 256>>>(wqh, wql, xh, xl, qkv_s, C3, CIN);
    }

    // 2+3) fused depthwise 5x5 + grouped pointwise -> agg
    {
        dim3 grid(4, PWG, BATCH);                // (4, 96, 16)
        dwpw<<<grid, 256>>>(qkv_s, w_dw, w_pw, agg_s);
    }

    // 4) attention -> transposed bf16 hi/lo
    relu_lin_att<<<BATCH * 64, 256>>>(qkv_s, agg_s, ah, al);

    // 5) proj GEMM (bf16 split) + BN: M=256, K=512
    {
        dim3 grid(HWN / 128, 256 / 128, BATCH);  // (32, 2, 16)
        gemm_mma<<<grid, 256>>>(wph, wpl, ah, al, out, 256, CATT,
                                gamma, beta, mean, var);
    }
}

// round 10
// speedup vs baseline: 1.4928x; 1.0485x over previous
#include <cuda_runtime.h>
#include <cuda_bf16.h>
#include <cstdint>

// Problem constants
#define BATCH 16
#define CIN   256
#define HWN   4096          // 64*64
#define C3    768           // 3*TOTAL
#define CATT  512           // 2*TOTAL
#define PWG   96

// ---------------------------------------------------------------------------
// Scratch (static device memory)
// ---------------------------------------------------------------------------
__device__ float g_qkv[BATCH * C3 * HWN];               // 201 MB
__device__ float g_agg[BATCH * C3 * HWN];               // 201 MB
__device__ float g_xT_hi[BATCH * HWN * CIN];            // 67 MB (tf32 bits)
__device__ float g_xT_lo[BATCH * HWN * CIN];            // 67 MB
__device__ __nv_bfloat16 g_attT_hi[BATCH * HWN * CATT]; // 67 MB
__device__ __nv_bfloat16 g_attT_lo[BATCH * HWN * CATT];
__device__ float g_wqkv_hi[C3 * CIN];
__device__ float g_wqkv_lo[C3 * CIN];
__device__ __nv_bfloat16 g_wproj_hi[256 * CATT];
__device__ __nv_bfloat16 g_wproj_lo[256 * CATT];

// ---------------------------------------------------------------------------
// Helpers
// ---------------------------------------------------------------------------
__device__ __forceinline__ uint32_t smem_u32(const void* p) {
    uint32_t a;
    asm("{ .reg .u64 t; cvta.to.shared.u64 t, %1; cvt.u32.u64 %0, t; }" : "=r"(a) : "l"(p));
    return a;
}
__device__ __forceinline__ void ldmx4(uint32_t* r, uint32_t addr) {
    asm volatile("ldmatrix.sync.aligned.m8n8.x4.shared.b16 {%0,%1,%2,%3}, [%4];"
                 : "=r"(r[0]), "=r"(r[1]), "=r"(r[2]), "=r"(r[3]) : "r"(addr));
}
__device__ __forceinline__ void ldmx2(uint32_t* r, uint32_t addr) {
    asm volatile("ldmatrix.sync.aligned.m8n8.x2.shared.b16 {%0,%1}, [%2];"
                 : "=r"(r[0]), "=r"(r[1]) : "r"(addr));
}
__device__ __forceinline__ void mma_bf16(float* d, const uint32_t* a, const uint32_t* b) {
    asm volatile(
        "mma.sync.aligned.m16n8k16.row.col.f32.bf16.bf16.f32 "
        "{%0,%1,%2,%3}, {%4,%5,%6,%7}, {%8,%9}, {%0,%1,%2,%3};"
        : "+f"(d[0]), "+f"(d[1]), "+f"(d[2]), "+f"(d[3])
        : "r"(a[0]), "r"(a[1]), "r"(a[2]), "r"(a[3]), "r"(b[0]), "r"(b[1]));
}
__device__ __forceinline__ void mma_tf32(float* d, const uint32_t* a, const uint32_t* b) {
    asm volatile(
        "mma.sync.aligned.m16n8k8.row.col.f32.tf32.tf32.f32 "
        "{%0,%1,%2,%3}, {%4,%5,%6,%7}, {%8,%9}, {%0,%1,%2,%3};"
        : "+f"(d[0]), "+f"(d[1]), "+f"(d[2]), "+f"(d[3])
        : "r"(a[0]), "r"(a[1]), "r"(a[2]), "r"(a[3]), "r"(b[0]), "r"(b[1]));
}
__device__ __forceinline__ float tf32_rna(float v) {
    uint32_t o;
    asm("cvt.rna.tf32.f32 %0, %1;" : "=r"(o) : "f"(v));
    return __uint_as_float(o);
}

// ---------------------------------------------------------------------------
// Splits
// ---------------------------------------------------------------------------
__global__ void split_bf16(const float* __restrict__ src,
                           __nv_bfloat16* __restrict__ hi,
                           __nv_bfloat16* __restrict__ lo, int n) {
    int i = blockIdx.x * 256 + threadIdx.x;
    if (i < n) {
        float v = src[i];
        __nv_bfloat16 h = __float2bfloat16(v);
        hi[i] = h;
        lo[i] = __float2bfloat16(v - __bfloat162float(h));
    }
}
__global__ void split_tf32(const float* __restrict__ src,
                           float* __restrict__ hi, float* __restrict__ lo, int n) {
    int i = blockIdx.x * 256 + threadIdx.x;
    if (i < n) {
        float v = src[i];
        float h = tf32_rna(v);
        hi[i] = h;
        lo[i] = tf32_rna(v - h);
    }
}

// ---------------------------------------------------------------------------
// Transpose + tf32-split x: [b][c][n] fp32 -> xT_hi/lo [b][n][c]
// ---------------------------------------------------------------------------
__global__ __launch_bounds__(256) void transpose_split_x(
    const float* __restrict__ x, float* __restrict__ xhi, float* __restrict__ xlo) {
    const int b = blockIdx.z;
    const int c0 = blockIdx.y * 64;
    const int n0 = blockIdx.x * 32;
    __shared__ float s[64][33];
    const int tid = threadIdx.x;
#pragma unroll
    for (int i = 0; i < 8; i++) {
        int u = tid + 256 * i;
        int cc = u >> 5, nn = u & 31;
        s[cc][nn] = x[((size_t)b * CIN + c0 + cc) * HWN + n0 + nn];
    }
    __syncthreads();
#pragma unroll
    for (int i = 0; i < 8; i++) {
        int u = tid + 256 * i;
        int cc = u & 63, nn = u >> 6;
        float v = s[cc][nn];
        float h = tf32_rna(v);
        size_t idx = ((size_t)b * HWN + n0 + nn) * CIN + c0 + cc;
        xhi[idx] = h;
        xlo[idx] = tf32_rna(v - h);
    }
}

// ---------------------------------------------------------------------------
// tf32 3-term split GEMM via mma.sync.m16n8k8.
//   C[b][m][n] = sum_k A[m][k]*B[b][n][k]   (terms hh + hl + lh)
// R10: CTA 128x128, BK=16, 4 warps (2x2), warp tile 64x64 (4x8 m16n8 tiles).
//   m_split=n_split=2 -> smem read bytes/chunk = 64KB (was 96KB with 8 warps).
//   A frags: LDSM.x4 per (mt, half); B frags: LDSM.x4 per nt-PAIR per half
//   (matrix slot i <- lanes 8i..8i+7: r0,r1 = nt even, r2,r3 = nt odd).
// ---------------------------------------------------------------------------
#define TLDS 20   // smem row stride in floats (16 + 4 pad)

__global__ __launch_bounds__(128, 2) void gemm_tf32(
    const float* __restrict__ Ahi, const float* __restrict__ Alo,
    const float* __restrict__ Bhi, const float* __restrict__ Blo,
    float* __restrict__ Cg, int M, int K) {
    __shared__ float As_hi[128 * TLDS];
    __shared__ float As_lo[128 * TLDS];
    __shared__ float Bs_hi[128 * TLDS];
    __shared__ float Bs_lo[128 * TLDS];

    const int tid = threadIdx.x;
    const int wid = tid >> 5;
    const int lane = tid & 31;

    const int b = blockIdx.z;
    const int m0 = blockIdx.y * 128;
    const int n0 = blockIdx.x * 128;

    const float* Bh = Bhi + (size_t)b * HWN * K;
    const float* Bl = Blo + (size_t)b * HWN * K;

    const int wm = (wid >> 1) * 64;   // warp M offset (2-way m split)
    const int wn = (wid & 1) * 64;    // warp N offset (2-way n split)

    const int qr = lane >> 2;    // 0..7
    const int qc = lane & 3;     // 0..3

    // A ldmatrix.x4 source coords: quadrants {row, row+8} x {k, k+4}
    const int aro = (lane & 7) + ((lane >> 3) & 1) * 8;
    const int aco = (lane >> 4) * 4;
    // B pair ldmatrix.x4 source coords: matrices = (nt_even k0-3),(nt_even k4-7),
    // (nt_odd k0-3),(nt_odd k4-7); lane group 8i feeds matrix i.
    const int bro = (lane & 7) + ((lane >> 4) & 1) * 8;   // row within 16-row pair
    const int bco = ((lane >> 3) & 1) * 4;                // k quadrant

    float acc[4][8][4];
#pragma unroll
    for (int mt = 0; mt < 4; mt++)
#pragma unroll
        for (int nt = 0; nt < 8; nt++)
#pragma unroll
            for (int r = 0; r < 4; r++) acc[mt][nt][r] = 0.f;

    for (int kc = 0; kc < K; kc += 16) {
        // load tiles (128 rows x 16 floats, hi+lo, A and B); 128 threads
#pragma unroll
        for (int i = 0; i < 4; i++) {
            int u = tid + 128 * i;      // 0..511
            int row = u >> 2;
            int c4 = (u & 3) << 2;      // 0,4,8,12
            size_t sa = (size_t)(m0 + row) * K + kc + c4;
            *(float4*)&As_hi[row * TLDS + c4] = *(const float4*)(Ahi + sa);
            *(float4*)&As_lo[row * TLDS + c4] = *(const float4*)(Alo + sa);
            size_t sb = (size_t)(n0 + row) * K + kc + c4;
            *(float4*)&Bs_hi[row * TLDS + c4] = *(const float4*)(Bh + sb);
            *(float4*)&Bs_lo[row * TLDS + c4] = *(const float4*)(Bl + sb);
        }
        __syncthreads();

#pragma unroll
        for (int kk = 0; kk < 16; kk += 8) {
            // B fragments: 4 nt-pairs, hi and lo, one LDSM.x4 each
            uint32_t bh[4][4], bl[4][4];
#pragma unroll
            for (int p = 0; p < 4; p++) {
                ldmx4(bh[p], smem_u32(&Bs_hi[(wn + p * 16 + bro) * TLDS + kk + bco]));
                ldmx4(bl[p], smem_u32(&Bs_lo[(wn + p * 16 + bro) * TLDS + kk + bco]));
            }
#pragma unroll
            for (int mt = 0; mt < 4; mt++) {
                uint32_t ah[4], al[4];
                ldmx4(ah, smem_u32(&As_hi[(wm + mt * 16 + aro) * TLDS + kk + aco]));
                ldmx4(al, smem_u32(&As_lo[(wm + mt * 16 + aro) * TLDS + kk + aco]));
#pragma unroll
                for (int p = 0; p < 4; p++) {
                    // nt even = regs [0,1], nt odd = regs [2,3]
                    mma_tf32(acc[mt][2 * p + 0], ah, &bh[p][0]);   // hh
                    mma_tf32(acc[mt][2 * p + 0], ah, &bl[p][0]);   // hl
                    mma_tf32(acc[mt][2 * p + 0], al, &bh[p][0]);   // lh
                    mma_tf32(acc[mt][2 * p + 1], ah, &bh[p][2]);
                    mma_tf32(acc[mt][2 * p + 1], ah, &bl[p][2]);
                    mma_tf32(acc[mt][2 * p + 1], al, &bh[p][2]);
                }
            }
        }
        __syncthreads();
    }

    // epilogue (m16n8 C layout)
#pragma unroll
    for (int mt = 0; mt < 4; mt++) {
        const int row0 = m0 + wm + mt * 16 + qr;
        const int row1 = row0 + 8;
        float* c0p = Cg + ((size_t)b * M + row0) * HWN + n0 + wn;
        float* c1p = Cg + ((size_t)b * M + row1) * HWN + n0 + wn;
        const int coff = qc << 1;
#pragma unroll
        for (int nt = 0; nt < 8; nt++) {
            *(float2*)(c0p + nt * 8 + coff) = make_float2(acc[mt][nt][0], acc[mt][nt][1]);
            *(float2*)(c1p + nt * 8 + coff) = make_float2(acc[mt][nt][2], acc[mt][nt][3]);
        }
    }
}

// ---------------------------------------------------------------------------
// bf16 3-term split GEMM (proj only) — proven version
// ---------------------------------------------------------------------------
#define BK  32
#define LDS 40

__global__ __launch_bounds__(256, 2) void gemm_mma(
    const __nv_bfloat16* __restrict__ Ahi, const __nv_bfloat16* __restrict__ Alo,
    const __nv_bfloat16* __restrict__ Bhi, const __nv_bfloat16* __restrict__ Blo,
    float* __restrict__ Cg, int M, int K,
    const float* __restrict__ gamma, const float* __restrict__ beta,
    const float* __restrict__ mean, const float* __restrict__ var) {
    __shared__ __nv_bfloat16 As_hi[128 * LDS];
    __shared__ __nv_bfloat16 As_lo[128 * LDS];
    __shared__ __nv_bfloat16 Bs_hi[128 * LDS];
    __shared__ __nv_bfloat16 Bs_lo[128 * LDS];

    const int tid = threadIdx.x;
    const int wid = tid >> 5;
    const int lane = tid & 31;

    const int b = blockIdx.z;
    const int m0 = blockIdx.y * 128;
    const int n0 = blockIdx.x * 128;

    const __nv_bfloat16* Bh = Bhi + (size_t)b * HWN * K;
    const __nv_bfloat16* Bl = Blo + (size_t)b * HWN * K;

    const int wm = (wid >> 2) * 64;
    const int wn = (wid & 3) * 32;

    const int ar = lane & 15, ac = (lane >> 4) << 3;
    const int br = lane & 7,  bc = ((lane >> 3) & 1) << 3;

    float acc[4][4][4];
#pragma unroll
    for (int mt = 0; mt < 4; mt++)
#pragma unroll
        for (int nt = 0; nt < 4; nt++)
#pragma unroll
            for (int r = 0; r < 4; r++) acc[mt][nt][r] = 0.f;

    for (int kc = 0; kc < K; kc += BK) {
#pragma unroll
        for (int i = 0; i < 2; i++) {
            int u = tid + 256 * i;
            int row = u >> 2;
            int cu = (u & 3) << 3;
            size_t sa = (size_t)(m0 + row) * K + kc + cu;
            *(uint4*)&As_hi[row * LDS + cu] = *(const uint4*)(Ahi + sa);
            *(uint4*)&As_lo[row * LDS + cu] = *(const uint4*)(Alo + sa);
            size_t sb = (size_t)(n0 + row) * K + kc + cu;
            *(uint4*)&Bs_hi[row * LDS + cu] = *(const uint4*)(Bh + sb);
            *(uint4*)&Bs_lo[row * LDS + cu] = *(const uint4*)(Bl + sb);
        }
        __syncthreads();

#pragma unroll
        for (int kk = 0; kk < BK; kk += 16) {
            uint32_t ah[4][4], bhf[4][2];
#pragma unroll
            for (int mt = 0; mt < 4; mt++)
                ldmx4(ah[mt], smem_u32(&As_hi[(wm + mt * 16 + ar) * LDS + kk + ac]));
#pragma unroll
            for (int nt = 0; nt < 4; nt++)
                ldmx2(bhf[nt], smem_u32(&Bs_hi[(wn + nt * 8 + br) * LDS + kk + bc]));
#pragma unroll
            for (int mt = 0; mt < 4; mt++)
#pragma unroll
                for (int nt = 0; nt < 4; nt++)
                    mma_bf16(acc[mt][nt], ah[mt], bhf[nt]);

            uint32_t al[4][4];
#pragma unroll
            for (int mt = 0; mt < 4; mt++)
                ldmx4(al[mt], smem_u32(&As_lo[(wm + mt * 16 + ar) * LDS + kk + ac]));
#pragma unroll
            for (int mt = 0; mt < 4; mt++)
#pragma unroll
                for (int nt = 0; nt < 4; nt++)
                    mma_bf16(acc[mt][nt], al[mt], bhf[nt]);

            uint32_t blf[4][2];
#pragma unroll
            for (int nt = 0; nt < 4; nt++)
                ldmx2(blf[nt], smem_u32(&Bs_lo[(wn + nt * 8 + br) * LDS + kk + bc]));
#pragma unroll
            for (int mt = 0; mt < 4; mt++)
#pragma unroll
                for (int nt = 0; nt < 4; nt++)
                    mma_bf16(acc[mt][nt], ah[mt], blf[nt]);
        }
        __syncthreads();
    }

#pragma unroll
    for (int mt = 0; mt < 4; mt++) {
        const int row0 = m0 + wm + mt * 16 + (lane >> 2);
        const int row1 = row0 + 8;
        float s0 = 1.f, o0 = 0.f, s1 = 1.f, o1 = 0.f;
        if (gamma) {
            float iv0 = gamma[row0] * rsqrtf(var[row0] + 1e-5f);
            s0 = iv0; o0 = beta[row0] - mean[row0] * iv0;
            float iv1 = gamma[row1] * rsqrtf(var[row1] + 1e-5f);
            s1 = iv1; o1 = beta[row1] - mean[row1] * iv1;
        }
        float* c0p = Cg + ((size_t)b * M + row0) * HWN + n0 + wn;
        float* c1p = Cg + ((size_t)b * M + row1) * HWN + n0 + wn;
        const int coff = ((lane & 3) << 1);
#pragma unroll
        for (int nt = 0; nt < 4; nt++) {
            float2 v0, v1;
            v0.x = acc[mt][nt][0] * s0 + o0;
            v0.y = acc[mt][nt][1] * s0 + o0;
            v1.x = acc[mt][nt][2] * s1 + o1;
            v1.y = acc[mt][nt][3] * s1 + o1;
            *(float2*)(c0p + nt * 8 + coff) = v0;
            *(float2*)(c1p + nt * 8 + coff) = v1;
        }
    }
}

// ---------------------------------------------------------------------------
// FUSED depthwise 5x5 (pad 2) + grouped 1x1 (8-ch groups).
// Block = (tile 32x32, group g, batch b). Thread = 1 column x 4-row strip.
// ---------------------------------------------------------------------------
__global__ __launch_bounds__(256) void dwpw(
    const float* __restrict__ qkv, const float* __restrict__ w_dw,
    const float* __restrict__ w_pw, float* __restrict__ agg) {
    const int tile = blockIdx.x;           // 0..3
    const int g = blockIdx.y;              // 0..95
    const int b = blockIdx.z;
    const int ty = (tile >> 1) * 32;
    const int tx = (tile & 1) * 32;

    __shared__ float h[8][36 * 36];
    __shared__ float wd[8][25];
    __shared__ float wp[64];

    const int tid = threadIdx.x;
    if (tid < 64) wp[tid] = w_pw[g * 64 + tid];
    if (tid < 200) {
        int c = tid / 25, t = tid % 25;
        wd[c][t] = w_dw[(g * 8 + c) * 25 + t];
    }

    const float* ip = qkv + ((size_t)b * C3 + (size_t)g * 8) * HWN;
    for (int idx = tid; idx < 8 * 1296; idx += 256) {
        int c = idx / 1296, rem = idx - c * 1296;
        int hy = rem / 36, hx = rem - hy * 36;
        int gy = ty + hy - 2, gx = tx + hx - 2;
        float v = 0.f;
        if ((unsigned)gy < 64u && (unsigned)gx < 64u) v = ip[(size_t)c * HWN + gy * 64 + gx];
        h[c][rem] = v;
    }
    __syncthreads();

    const int lx = tid & 31;          // column
    const int sy = (tid >> 5) << 2;   // strip row base (0,4,...,28)

    float d[8][4];
#pragma unroll
    for (int c = 0; c < 8; c++) {
        float a0 = 0.f, a1 = 0.f, a2 = 0.f, a3 = 0.f;
#pragma unroll
        for (int r = 0; r < 8; r++) {
            const float* hp = &h[c][(sy + r) * 36 + lx];
            float v0 = hp[0], v1 = hp[1], v2 = hp[2], v3 = hp[3], v4 = hp[4];
#pragma unroll
            for (int j = 0; j < 4; j++) {
                int dy = r - j;
                if (dy >= 0 && dy < 5) {
                    float s = v0 * wd[c][dy * 5 + 0];
                    s = fmaf(v1, wd[c][dy * 5 + 1], s);
                    s = fmaf(v2, wd[c][dy * 5 + 2], s);
                    s = fmaf(v3, wd[c][dy * 5 + 3], s);
                    s = fmaf(v4, wd[c][dy * 5 + 4], s);
                    if (j == 0) a0 += s;
                    else if (j == 1) a1 += s;
                    else if (j == 2) a2 += s;
                    else a3 += s;
                }
            }
        }
        d[c][0] = a0; d[c][1] = a1; d[c][2] = a2; d[c][3] = a3;
    }

    float* op = agg + ((size_t)b * C3 + (size_t)g * 8) * HWN;
#pragma unroll
    for (int j = 0; j < 4; j++) {
        size_t pbase = (size_t)(ty + sy + j) * 64 + tx + lx;
#pragma unroll
        for (int o = 0; o < 8; o++) {
            float s = 0.f;
#pragma unroll
            for (int c = 0; c < 8; c++) s = fmaf(wp[o * 8 + c], d[c][j], s);
            op[(size_t)o * HWN + pbase] = s;
        }
    }
}

// ---------------------------------------------------------------------------
// ReLU linear attention. Pass 1: warp w owns k-channel d=w (kv row in regs,
// shuffle-reduced, no atomics). Pass 2: float4 q loads, bf16 hi/lo transposed
// output (proj B operand).
// ---------------------------------------------------------------------------
__global__ __launch_bounds__(256) void relu_lin_att(
    const float* __restrict__ qkv, const float* __restrict__ agg,
    __nv_bfloat16* __restrict__ ohi, __nv_bfloat16* __restrict__ olo) {
    const int bg = blockIdx.x;
    const int b = bg >> 6;
    const int g = bg & 63;
    const float* base = (g < 32)
        ? qkv + ((size_t)b * C3 + (size_t)g * 24) * HWN
        : agg + ((size_t)b * C3 + (size_t)(g - 32) * 24) * HWN;

    __shared__ float kvs[72];
    const int tid = threadIdx.x;
    const int w = tid >> 5;        // warp = k-channel d
    const int lane = tid & 31;

    float kvr[9];
#pragma unroll
    for (int i = 0; i < 9; i++) kvr[i] = 0.f;

    const float* kch = base + (size_t)(8 + w) * HWN;
    for (int n4 = lane * 4; n4 < HWN; n4 += 128) {
        float4 kk = *(const float4*)(kch + n4);
        kk.x = fmaxf(kk.x, 0.f); kk.y = fmaxf(kk.y, 0.f);
        kk.z = fmaxf(kk.z, 0.f); kk.w = fmaxf(kk.w, 0.f);
#pragma unroll
        for (int e = 0; e < 8; e++) {
            float4 vv = *(const float4*)(base + (size_t)(16 + e) * HWN + n4);
            kvr[e] = fmaf(kk.x, vv.x, kvr[e]);
            kvr[e] = fmaf(kk.y, vv.y, kvr[e]);
            kvr[e] = fmaf(kk.z, vv.z, kvr[e]);
            kvr[e] = fmaf(kk.w, vv.w, kvr[e]);
        }
        kvr[8] += kk.x + kk.y + kk.z + kk.w;
    }
#pragma unroll
    for (int i = 0; i < 9; i++) {
        float v = kvr[i];
        v += __shfl_xor_sync(0xffffffffu, v, 16);
        v += __shfl_xor_sync(0xffffffffu, v, 8);
        v += __shfl_xor_sync(0xffffffffu, v, 4);
        v += __shfl_xor_sync(0xffffffffu, v, 2);
        v += __shfl_xor_sync(0xffffffffu, v, 1);
        if (lane == 0) kvs[w * 9 + i] = v;
    }
    __syncthreads();

    for (int n4 = tid * 4; n4 < HWN; n4 += 1024) {
        float4 q4[8];
#pragma unroll
        for (int d0 = 0; d0 < 8; d0++) {
            float4 q = *(const float4*)(base + (size_t)d0 * HWN + n4);
            q.x = fmaxf(q.x, 0.f); q.y = fmaxf(q.y, 0.f);
            q.z = fmaxf(q.z, 0.f); q.w = fmaxf(q.w, 0.f);
            q4[d0] = q;
        }
#pragma unroll
        for (int px = 0; px < 4; px++) {
            float qd[8];
#pragma unroll
            for (int d0 = 0; d0 < 8; d0++)
                qd[d0] = px == 0 ? q4[d0].x : px == 1 ? q4[d0].y : px == 2 ? q4[d0].z : q4[d0].w;
            float den = 0.f;
#pragma unroll
            for (int d0 = 0; d0 < 8; d0++) den = fmaf(qd[d0], kvs[d0 * 9 + 8], den);
            float rden = 1.f / (den + 1e-15f);
            __align__(16) __nv_bfloat16 hi[8], lo[8];
#pragma unroll
            for (int e = 0; e < 8; e++) {
                float num = 0.f;
#pragma unroll
                for (int d0 = 0; d0 < 8; d0++) num = fmaf(qd[d0], kvs[d0 * 9 + e], num);
                float v = num * rden;
                __nv_bfloat16 hh = __float2bfloat16(v);
                hi[e] = hh;
                lo[e] = __float2bfloat16(v - __bfloat162float(hh));
            }
            size_t idx = ((size_t)b * HWN + n4 + px) * CATT + g * 8;
            *(uint4*)(ohi + idx) = *(const uint4*)hi;
            *(uint4*)(olo + idx) = *(const uint4*)lo;
        }
    }
}

// ---------------------------------------------------------------------------
// Launch
// ---------------------------------------------------------------------------
extern "C" void kernel_launch(void* const* d_in, const int* in_sizes, int n_in,
                              void* d_out, int out_size) {
    const float* x      = (const float*)d_in[0];
    const float* w_qkv  = (const float*)d_in[1];
    const float* w_dw   = (const float*)d_in[2];
    const float* w_pw   = (const float*)d_in[3];
    const float* w_proj = (const float*)d_in[4];
    const float* gamma  = (const float*)d_in[5];
    const float* beta   = (const float*)d_in[6];
    const float* mean   = (const float*)d_in[7];
    const float* var    = (const float*)d_in[8];
    float* out = (float*)d_out;

    float *qkv_s, *agg_s, *xh, *xl, *wqh, *wql;
    __nv_bfloat16 *ah, *al, *wph, *wpl;
    cudaGetSymbolAddress((void**)&qkv_s, g_qkv);
    cudaGetSymbolAddress((void**)&agg_s, g_agg);
    cudaGetSymbolAddress((void**)&xh, g_xT_hi);
    cudaGetSymbolAddress((void**)&xl, g_xT_lo);
    cudaGetSymbolAddress((void**)&ah, g_attT_hi);
    cudaGetSymbolAddress((void**)&al, g_attT_lo);
    cudaGetSymbolAddress((void**)&wqh, g_wqkv_hi);
    cudaGetSymbolAddress((void**)&wql, g_wqkv_lo);
    cudaGetSymbolAddress((void**)&wph, g_wproj_hi);
    cudaGetSymbolAddress((void**)&wpl, g_wproj_lo);

    // 0) weight splits + x transpose/split
    split_tf32<<<(C3 * CIN + 255) / 256, 256>>>(w_qkv, wqh, wql, C3 * CIN);
    split_bf16<<<(256 * CATT + 255) / 256, 256>>>(w_proj, wph, wpl, 256 * CATT);
    {
        dim3 grid(HWN / 32, CIN / 64, BATCH);
        transpose_split_x<<<grid, 256>>>(x, xh, xl);
    }

    // 1) qkv GEMM (tf32 split): M=768, K=256 — 128 threads, 4 warps
    {
        dim3 grid(HWN / 128, C3 / 128, BATCH);   // (32, 6, 16)
        gemm_tf32<<<grid, 128>>>(wqh, wql, xh, xl, qkv_s, C3, CIN);
    }

    // 2+3) fused depthwise 5x5 + grouped pointwise -> agg
    {
        dim3 grid(4, PWG, BATCH);                // (4, 96, 16)
        dwpw<<<grid, 256>>>(qkv_s, w_dw, w_pw, agg_s);
    }

    // 4) attention -> transposed bf16 hi/lo
    relu_lin_att<<<BATCH * 64, 256>>>(qkv_s, agg_s, ah, al);

    // 5) proj GEMM (bf16 split) + BN: M=256, K=512
    {
        dim3 grid(HWN / 128, 256 / 128, BATCH);  // (32, 2, 16)
        gemm_mma<<<grid, 256>>>(wph, wpl, ah, al, out, 256, CATT,
                                gamma, beta, mean, var);
    }
}

// round 11
// speedup vs baseline: 1.8264x; 1.2235x over previous
#include <cuda_runtime.h>
#include <cuda_bf16.h>
#include <cuda_fp16.h>
#include <cstdint>

// Problem constants
#define BATCH 16
#define CIN   256
#define HWN   4096          // 64*64
#define C3    768           // 3*TOTAL
#define CATT  512           // 2*TOTAL
#define PWG   96

// ---------------------------------------------------------------------------
// Scratch (static device memory)
// ---------------------------------------------------------------------------
__device__ float g_qkv[BATCH * C3 * HWN];               // 201 MB
__device__ float g_agg[BATCH * C3 * HWN];               // 201 MB
__device__ __half g_xT_hi[BATCH * HWN * CIN];           // 33.5 MB
__device__ __half g_xT_lo[BATCH * HWN * CIN];
__device__ __nv_bfloat16 g_attT_hi[BATCH * HWN * CATT]; // 67 MB
__device__ __nv_bfloat16 g_attT_lo[BATCH * HWN * CATT];
__device__ __half g_wqkv_hi[C3 * CIN];
__device__ __half g_wqkv_lo[C3 * CIN];
__device__ __nv_bfloat16 g_wproj_hi[256 * CATT];
__device__ __nv_bfloat16 g_wproj_lo[256 * CATT];

// ---------------------------------------------------------------------------
// Helpers
// ---------------------------------------------------------------------------
__device__ __forceinline__ uint32_t smem_u32(const void* p) {
    uint32_t a;
    asm("{ .reg .u64 t; cvta.to.shared.u64 t, %1; cvt.u32.u64 %0, t; }" : "=r"(a) : "l"(p));
    return a;
}
__device__ __forceinline__ void ldmx4(uint32_t* r, uint32_t addr) {
    asm volatile("ldmatrix.sync.aligned.m8n8.x4.shared.b16 {%0,%1,%2,%3}, [%4];"
                 : "=r"(r[0]), "=r"(r[1]), "=r"(r[2]), "=r"(r[3]) : "r"(addr));
}
__device__ __forceinline__ void ldmx2(uint32_t* r, uint32_t addr) {
    asm volatile("ldmatrix.sync.aligned.m8n8.x2.shared.b16 {%0,%1}, [%2];"
                 : "=r"(r[0]), "=r"(r[1]) : "r"(addr));
}
__device__ __forceinline__ void mma_bf16(float* d, const uint32_t* a, const uint32_t* b) {
    asm volatile(
        "mma.sync.aligned.m16n8k16.row.col.f32.bf16.bf16.f32 "
        "{%0,%1,%2,%3}, {%4,%5,%6,%7}, {%8,%9}, {%0,%1,%2,%3};"
        : "+f"(d[0]), "+f"(d[1]), "+f"(d[2]), "+f"(d[3])
        : "r"(a[0]), "r"(a[1]), "r"(a[2]), "r"(a[3]), "r"(b[0]), "r"(b[1]));
}
__device__ __forceinline__ void mma_f16(float* d, const uint32_t* a, const uint32_t* b) {
    asm volatile(
        "mma.sync.aligned.m16n8k16.row.col.f32.f16.f16.f32 "
        "{%0,%1,%2,%3}, {%4,%5,%6,%7}, {%8,%9}, {%0,%1,%2,%3};"
        : "+f"(d[0]), "+f"(d[1]), "+f"(d[2]), "+f"(d[3])
        : "r"(a[0]), "r"(a[1]), "r"(a[2]), "r"(a[3]), "r"(b[0]), "r"(b[1]));
}

// ---------------------------------------------------------------------------
// Splits
// ---------------------------------------------------------------------------
__global__ void split_bf16(const float* __restrict__ src,
                           __nv_bfloat16* __restrict__ hi,
                           __nv_bfloat16* __restrict__ lo, int n) {
    int i = blockIdx.x * 256 + threadIdx.x;
    if (i < n) {
        float v = src[i];
        __nv_bfloat16 h = __float2bfloat16(v);
        hi[i] = h;
        lo[i] = __float2bfloat16(v - __bfloat162float(h));
    }
}
__global__ void split_f16(const float* __restrict__ src,
                          __half* __restrict__ hi, __half* __restrict__ lo, int n) {
    int i = blockIdx.x * 256 + threadIdx.x;
    if (i < n) {
        float v = src[i];
        __half h = __float2half_rn(v);
        hi[i] = h;
        lo[i] = __float2half_rn(v - __half2float(h));
    }
}

// ---------------------------------------------------------------------------
// Transpose + fp16-split x: [b][c][n] fp32 -> xT_hi/lo [b][n][c]
// ---------------------------------------------------------------------------
__global__ __launch_bounds__(256) void transpose_split_x(
    const float* __restrict__ x, __half* __restrict__ xhi, __half* __restrict__ xlo) {
    const int b = blockIdx.z;
    const int c0 = blockIdx.y * 64;
    const int n0 = blockIdx.x * 32;
    __shared__ float s[64][33];
    const int tid = threadIdx.x;
#pragma unroll
    for (int i = 0; i < 8; i++) {
        int u = tid + 256 * i;
        int cc = u >> 5, nn = u & 31;
        s[cc][nn] = x[((size_t)b * CIN + c0 + cc) * HWN + n0 + nn];
    }
    __syncthreads();
#pragma unroll
    for (int i = 0; i < 8; i++) {
        int u = tid + 256 * i;
        int cc = u & 63, nn = u >> 6;
        float v = s[cc][nn];
        __half h = __float2half_rn(v);
        size_t idx = ((size_t)b * HWN + n0 + nn) * CIN + c0 + cc;
        xhi[idx] = h;
        xlo[idx] = __float2half_rn(v - __half2float(h));
    }
}

// ---------------------------------------------------------------------------
// fp16 3-term split GEMM (qkv): C[b][m][n] = sum_k A[m][k]*B[b][n][k]
// Identical geometry to the proven bf16 gemm_mma: 256 thr, 8 warps (2x4),
// warp 64x32, BK=32, LDS=40 pad, ldmatrix fragments. Terms hh + hl + lh.
// ---------------------------------------------------------------------------
#define BK  32
#define LDS 40

__global__ __launch_bounds__(256, 2) void gemm_f16(
    const __half* __restrict__ Ahi, const __half* __restrict__ Alo,
    const __half* __restrict__ Bhi, const __half* __restrict__ Blo,
    float* __restrict__ Cg, int M, int K) {
    __shared__ __half As_hi[128 * LDS];
    __shared__ __half As_lo[128 * LDS];
    __shared__ __half Bs_hi[128 * LDS];
    __shared__ __half Bs_lo[128 * LDS];

    const int tid = threadIdx.x;
    const int wid = tid >> 5;
    const int lane = tid & 31;

    const int b = blockIdx.z;
    const int m0 = blockIdx.y * 128;
    const int n0 = blockIdx.x * 128;

    const __half* Bh = Bhi + (size_t)b * HWN * K;
    const __half* Bl = Blo + (size_t)b * HWN * K;

    const int wm = (wid >> 2) * 64;
    const int wn = (wid & 3) * 32;

    const int ar = lane & 15, ac = (lane >> 4) << 3;
    const int br = lane & 7,  bc = ((lane >> 3) & 1) << 3;

    float acc[4][4][4];
#pragma unroll
    for (int mt = 0; mt < 4; mt++)
#pragma unroll
        for (int nt = 0; nt < 4; nt++)
#pragma unroll
            for (int r = 0; r < 4; r++) acc[mt][nt][r] = 0.f;

    for (int kc = 0; kc < K; kc += BK) {
#pragma unroll
        for (int i = 0; i < 2; i++) {
            int u = tid + 256 * i;
            int row = u >> 2;
            int cu = (u & 3) << 3;
            size_t sa = (size_t)(m0 + row) * K + kc + cu;
            *(uint4*)&As_hi[row * LDS + cu] = *(const uint4*)(Ahi + sa);
            *(uint4*)&As_lo[row * LDS + cu] = *(const uint4*)(Alo + sa);
            size_t sb = (size_t)(n0 + row) * K + kc + cu;
            *(uint4*)&Bs_hi[row * LDS + cu] = *(const uint4*)(Bh + sb);
            *(uint4*)&Bs_lo[row * LDS + cu] = *(const uint4*)(Bl + sb);
        }
        __syncthreads();

#pragma unroll
        for (int kk = 0; kk < BK; kk += 16) {
            uint32_t ah[4][4], bhf[4][2];
#pragma unroll
            for (int mt = 0; mt < 4; mt++)
                ldmx4(ah[mt], smem_u32(&As_hi[(wm + mt * 16 + ar) * LDS + kk + ac]));
#pragma unroll
            for (int nt = 0; nt < 4; nt++)
                ldmx2(bhf[nt], smem_u32(&Bs_hi[(wn + nt * 8 + br) * LDS + kk + bc]));
#pragma unroll
            for (int mt = 0; mt < 4; mt++)
#pragma unroll
                for (int nt = 0; nt < 4; nt++)
                    mma_f16(acc[mt][nt], ah[mt], bhf[nt]);

            uint32_t al[4][4];
#pragma unroll
            for (int mt = 0; mt < 4; mt++)
                ldmx4(al[mt], smem_u32(&As_lo[(wm + mt * 16 + ar) * LDS + kk + ac]));
#pragma unroll
            for (int mt = 0; mt < 4; mt++)
#pragma unroll
                for (int nt = 0; nt < 4; nt++)
                    mma_f16(acc[mt][nt], al[mt], bhf[nt]);

            uint32_t blf[4][2];
#pragma unroll
            for (int nt = 0; nt < 4; nt++)
                ldmx2(blf[nt], smem_u32(&Bs_lo[(wn + nt * 8 + br) * LDS + kk + bc]));
#pragma unroll
            for (int mt = 0; mt < 4; mt++)
#pragma unroll
                for (int nt = 0; nt < 4; nt++)
                    mma_f16(acc[mt][nt], ah[mt], blf[nt]);
        }
        __syncthreads();
    }

#pragma unroll
    for (int mt = 0; mt < 4; mt++) {
        const int row0 = m0 + wm + mt * 16 + (lane >> 2);
        const int row1 = row0 + 8;
        float* c0p = Cg + ((size_t)b * M + row0) * HWN + n0 + wn;
        float* c1p = Cg + ((size_t)b * M + row1) * HWN + n0 + wn;
        const int coff = ((lane & 3) << 1);
#pragma unroll
        for (int nt = 0; nt < 4; nt++) {
            *(float2*)(c0p + nt * 8 + coff) = make_float2(acc[mt][nt][0], acc[mt][nt][1]);
            *(float2*)(c1p + nt * 8 + coff) = make_float2(acc[mt][nt][2], acc[mt][nt][3]);
        }
    }
}

// ---------------------------------------------------------------------------
// bf16 3-term split GEMM (proj) — proven version with BN epilogue
// ---------------------------------------------------------------------------
__global__ __launch_bounds__(256, 2) void gemm_mma(
    const __nv_bfloat16* __restrict__ Ahi, const __nv_bfloat16* __restrict__ Alo,
    const __nv_bfloat16* __restrict__ Bhi, const __nv_bfloat16* __restrict__ Blo,
    float* __restrict__ Cg, int M, int K,
    const float* __restrict__ gamma, const float* __restrict__ beta,
    const float* __restrict__ mean, const float* __restrict__ var) {
    __shared__ __nv_bfloat16 As_hi[128 * LDS];
    __shared__ __nv_bfloat16 As_lo[128 * LDS];
    __shared__ __nv_bfloat16 Bs_hi[128 * LDS];
    __shared__ __nv_bfloat16 Bs_lo[128 * LDS];

    const int tid = threadIdx.x;
    const int wid = tid >> 5;
    const int lane = tid & 31;

    const int b = blockIdx.z;
    const int m0 = blockIdx.y * 128;
    const int n0 = blockIdx.x * 128;

    const __nv_bfloat16* Bh = Bhi + (size_t)b * HWN * K;
    const __nv_bfloat16* Bl = Blo + (size_t)b * HWN * K;

    const int wm = (wid >> 2) * 64;
    const int wn = (wid & 3) * 32;

    const int ar = lane & 15, ac = (lane >> 4) << 3;
    const int br = lane & 7,  bc = ((lane >> 3) & 1) << 3;

    float acc[4][4][4];
#pragma unroll
    for (int mt = 0; mt < 4; mt++)
#pragma unroll
        for (int nt = 0; nt < 4; nt++)
#pragma unroll
            for (int r = 0; r < 4; r++) acc[mt][nt][r] = 0.f;

    for (int kc = 0; kc < K; kc += BK) {
#pragma unroll
        for (int i = 0; i < 2; i++) {
            int u = tid + 256 * i;
            int row = u >> 2;
            int cu = (u & 3) << 3;
            size_t sa = (size_t)(m0 + row) * K + kc + cu;
            *(uint4*)&As_hi[row * LDS + cu] = *(const uint4*)(Ahi + sa);
            *(uint4*)&As_lo[row * LDS + cu] = *(const uint4*)(Alo + sa);
            size_t sb = (size_t)(n0 + row) * K + kc + cu;
            *(uint4*)&Bs_hi[row * LDS + cu] = *(const uint4*)(Bh + sb);
            *(uint4*)&Bs_lo[row * LDS + cu] = *(const uint4*)(Bl + sb);
        }
        __syncthreads();

#pragma unroll
        for (int kk = 0; kk < BK; kk += 16) {
            uint32_t ah[4][4], bhf[4][2];
#pragma unroll
            for (int mt = 0; mt < 4; mt++)
                ldmx4(ah[mt], smem_u32(&As_hi[(wm + mt * 16 + ar) * LDS + kk + ac]));
#pragma unroll
            for (int nt = 0; nt < 4; nt++)
                ldmx2(bhf[nt], smem_u32(&Bs_hi[(wn + nt * 8 + br) * LDS + kk + bc]));
#pragma unroll
            for (int mt = 0; mt < 4; mt++)
#pragma unroll
                for (int nt = 0; nt < 4; nt++)
                    mma_bf16(acc[mt][nt], ah[mt], bhf[nt]);

            uint32_t al[4][4];
#pragma unroll
            for (int mt = 0; mt < 4; mt++)
                ldmx4(al[mt], smem_u32(&As_lo[(wm + mt * 16 + ar) * LDS + kk + ac]));
#pragma unroll
            for (int mt = 0; mt < 4; mt++)
#pragma unroll
                for (int nt = 0; nt < 4; nt++)
                    mma_bf16(acc[mt][nt], al[mt], bhf[nt]);

            uint32_t blf[4][2];
#pragma unroll
            for (int nt = 0; nt < 4; nt++)
                ldmx2(blf[nt], smem_u32(&Bs_lo[(wn + nt * 8 + br) * LDS + kk + bc]));
#pragma unroll
            for (int mt = 0; mt < 4; mt++)
#pragma unroll
                for (int nt = 0; nt < 4; nt++)
                    mma_bf16(acc[mt][nt], ah[mt], blf[nt]);
        }
        __syncthreads();
    }

#pragma unroll
    for (int mt = 0; mt < 4; mt++) {
        const int row0 = m0 + wm + mt * 16 + (lane >> 2);
        const int row1 = row0 + 8;
        float s0 = 1.f, o0 = 0.f, s1 = 1.f, o1 = 0.f;
        if (gamma) {
            float iv0 = gamma[row0] * rsqrtf(var[row0] + 1e-5f);
            s0 = iv0; o0 = beta[row0] - mean[row0] * iv0;
            float iv1 = gamma[row1] * rsqrtf(var[row1] + 1e-5f);
            s1 = iv1; o1 = beta[row1] - mean[row1] * iv1;
        }
        float* c0p = Cg + ((size_t)b * M + row0) * HWN + n0 + wn;
        float* c1p = Cg + ((size_t)b * M + row1) * HWN + n0 + wn;
        const int coff = ((lane & 3) << 1);
#pragma unroll
        for (int nt = 0; nt < 4; nt++) {
            float2 v0, v1;
            v0.x = acc[mt][nt][0] * s0 + o0;
            v0.y = acc[mt][nt][1] * s0 + o0;
            v1.x = acc[mt][nt][2] * s1 + o1;
            v1.y = acc[mt][nt][3] * s1 + o1;
            *(float2*)(c0p + nt * 8 + coff) = v0;
            *(float2*)(c1p + nt * 8 + coff) = v1;
        }
    }
}

// ---------------------------------------------------------------------------
// FUSED depthwise 5x5 (pad 2) + grouped 1x1 (8-ch groups).
// ---------------------------------------------------------------------------
__global__ __launch_bounds__(256) void dwpw(
    const float* __restrict__ qkv, const float* __restrict__ w_dw,
    const float* __restrict__ w_pw, float* __restrict__ agg) {
    const int tile = blockIdx.x;           // 0..3
    const int g = blockIdx.y;              // 0..95
    const int b = blockIdx.z;
    const int ty = (tile >> 1) * 32;
    const int tx = (tile & 1) * 32;

    __shared__ float h[8][36 * 36];
    __shared__ float wd[8][25];
    __shared__ float wp[64];

    const int tid = threadIdx.x;
    if (tid < 64) wp[tid] = w_pw[g * 64 + tid];
    if (tid < 200) {
        int c = tid / 25, t = tid % 25;
        wd[c][t] = w_dw[(g * 8 + c) * 25 + t];
    }

    const float* ip = qkv + ((size_t)b * C3 + (size_t)g * 8) * HWN;
    for (int idx = tid; idx < 8 * 1296; idx += 256) {
        int c = idx / 1296, rem = idx - c * 1296;
        int hy = rem / 36, hx = rem - hy * 36;
        int gy = ty + hy - 2, gx = tx + hx - 2;
        float v = 0.f;
        if ((unsigned)gy < 64u && (unsigned)gx < 64u) v = ip[(size_t)c * HWN + gy * 64 + gx];
        h[c][rem] = v;
    }
    __syncthreads();

    const int lx = tid & 31;
    const int sy = (tid >> 5) << 2;

    float d[8][4];
#pragma unroll
    for (int c = 0; c < 8; c++) {
        float a0 = 0.f, a1 = 0.f, a2 = 0.f, a3 = 0.f;
#pragma unroll
        for (int r = 0; r < 8; r++) {
            const float* hp = &h[c][(sy + r) * 36 + lx];
            float v0 = hp[0], v1 = hp[1], v2 = hp[2], v3 = hp[3], v4 = hp[4];
#pragma unroll
            for (int j = 0; j < 4; j++) {
                int dy = r - j;
                if (dy >= 0 && dy < 5) {
                    float s = v0 * wd[c][dy * 5 + 0];
                    s = fmaf(v1, wd[c][dy * 5 + 1], s);
                    s = fmaf(v2, wd[c][dy * 5 + 2], s);
                    s = fmaf(v3, wd[c][dy * 5 + 3], s);
                    s = fmaf(v4, wd[c][dy * 5 + 4], s);
                    if (j == 0) a0 += s;
                    else if (j == 1) a1 += s;
                    else if (j == 2) a2 += s;
                    else a3 += s;
                }
            }
        }
        d[c][0] = a0; d[c][1] = a1; d[c][2] = a2; d[c][3] = a3;
    }

    float* op = agg + ((size_t)b * C3 + (size_t)g * 8) * HWN;
#pragma unroll
    for (int j = 0; j < 4; j++) {
        size_t pbase = (size_t)(ty + sy + j) * 64 + tx + lx;
#pragma unroll
        for (int o = 0; o < 8; o++) {
            float s = 0.f;
#pragma unroll
            for (int c = 0; c < 8; c++) s = fmaf(wp[o * 8 + c], d[c][j], s);
            op[(size_t)o * HWN + pbase] = s;
        }
    }
}

// ---------------------------------------------------------------------------
// ReLU linear attention (proven R8 version).
// ---------------------------------------------------------------------------
__global__ __launch_bounds__(256) void relu_lin_att(
    const float* __restrict__ qkv, const float* __restrict__ agg,
    __nv_bfloat16* __restrict__ ohi, __nv_bfloat16* __restrict__ olo) {
    const int bg = blockIdx.x;
    const int b = bg >> 6;
    const int g = bg & 63;
    const float* base = (g < 32)
        ? qkv + ((size_t)b * C3 + (size_t)g * 24) * HWN
        : agg + ((size_t)b * C3 + (size_t)(g - 32) * 24) * HWN;

    __shared__ float kvs[72];
    const int tid = threadIdx.x;
    const int w = tid >> 5;
    const int lane = tid & 31;

    float kvr[9];
#pragma unroll
    for (int i = 0; i < 9; i++) kvr[i] = 0.f;

    const float* kch = base + (size_t)(8 + w) * HWN;
    for (int n4 = lane * 4; n4 < HWN; n4 += 128) {
        float4 kk = *(const float4*)(kch + n4);
        kk.x = fmaxf(kk.x, 0.f); kk.y = fmaxf(kk.y, 0.f);
        kk.z = fmaxf(kk.z, 0.f); kk.w = fmaxf(kk.w, 0.f);
#pragma unroll
        for (int e = 0; e < 8; e++) {
            float4 vv = *(const float4*)(base + (size_t)(16 + e) * HWN + n4);
            kvr[e] = fmaf(kk.x, vv.x, kvr[e]);
            kvr[e] = fmaf(kk.y, vv.y, kvr[e]);
            kvr[e] = fmaf(kk.z, vv.z, kvr[e]);
            kvr[e] = fmaf(kk.w, vv.w, kvr[e]);
        }
        kvr[8] += kk.x + kk.y + kk.z + kk.w;
    }
#pragma unroll
    for (int i = 0; i < 9; i++) {
        float v = kvr[i];
        v += __shfl_xor_sync(0xffffffffu, v, 16);
        v += __shfl_xor_sync(0xffffffffu, v, 8);
        v += __shfl_xor_sync(0xffffffffu, v, 4);
        v += __shfl_xor_sync(0xffffffffu, v, 2);
        v += __shfl_xor_sync(0xffffffffu, v, 1);
        if (lane == 0) kvs[w * 9 + i] = v;
    }
    __syncthreads();

    for (int n4 = tid * 4; n4 < HWN; n4 += 1024) {
        float4 q4[8];
#pragma unroll
        for (int d0 = 0; d0 < 8; d0++) {
            float4 q = *(const float4*)(base + (size_t)d0 * HWN + n4);
            q.x = fmaxf(q.x, 0.f); q.y = fmaxf(q.y, 0.f);
            q.z = fmaxf(q.z, 0.f); q.w = fmaxf(q.w, 0.f);
            q4[d0] = q;
        }
#pragma unroll
        for (int px = 0; px < 4; px++) {
            float qd[8];
#pragma unroll
            for (int d0 = 0; d0 < 8; d0++)
                qd[d0] = px == 0 ? q4[d0].x : px == 1 ? q4[d0].y : px == 2 ? q4[d0].z : q4[d0].w;
            float den = 0.f;
#pragma unroll
            for (int d0 = 0; d0 < 8; d0++) den = fmaf(qd[d0], kvs[d0 * 9 + 8], den);
            float rden = 1.f / (den + 1e-15f);
            __align__(16) __nv_bfloat16 hi[8], lo[8];
#pragma unroll
            for (int e = 0; e < 8; e++) {
                float num = 0.f;
#pragma unroll
                for (int d0 = 0; d0 < 8; d0++) num = fmaf(qd[d0], kvs[d0 * 9 + e], num);
                float v = num * rden;
                __nv_bfloat16 hh = __float2bfloat16(v);
                hi[e] = hh;
                lo[e] = __float2bfloat16(v - __bfloat162float(hh));
            }
            size_t idx = ((size_t)b * HWN + n4 + px) * CATT + g * 8;
            *(uint4*)(ohi + idx) = *(const uint4*)hi;
            *(uint4*)(olo + idx) = *(const uint4*)lo;
        }
    }
}

// ---------------------------------------------------------------------------
// Launch
// ---------------------------------------------------------------------------
extern "C" void kernel_launch(void* const* d_in, const int* in_sizes, int n_in,
                              void* d_out, int out_size) {
    const float* x      = (const float*)d_in[0];
    const float* w_qkv  = (const float*)d_in[1];
    const float* w_dw   = (const float*)d_in[2];
    const float* w_pw   = (const float*)d_in[3];
    const float* w_proj = (const float*)d_in[4];
    const float* gamma  = (const float*)d_in[5];
    const float* beta   = (const float*)d_in[6];
    const float* mean   = (const float*)d_in[7];
    const float* var    = (const float*)d_in[8];
    float* out = (float*)d_out;

    float *qkv_s, *agg_s;
    __half *xh, *xl, *wqh, *wql;
    __nv_bfloat16 *ah, *al, *wph, *wpl;
    cudaGetSymbolAddress((void**)&qkv_s, g_qkv);
    cudaGetSymbolAddress((void**)&agg_s, g_agg);
    cudaGetSymbolAddress((void**)&xh, g_xT_hi);
    cudaGetSymbolAddress((void**)&xl, g_xT_lo);
    cudaGetSymbolAddress((void**)&ah, g_attT_hi);
    cudaGetSymbolAddress((void**)&al, g_attT_lo);
    cudaGetSymbolAddress((void**)&wqh, g_wqkv_hi);
    cudaGetSymbolAddress((void**)&wql, g_wqkv_lo);
    cudaGetSymbolAddress((void**)&wph, g_wproj_hi);
    cudaGetSymbolAddress((void**)&wpl, g_wproj_lo);

    // 0) weight splits + x transpose/split
    split_f16<<<(C3 * CIN + 255) / 256, 256>>>(w_qkv, wqh, wql, C3 * CIN);
    split_bf16<<<(256 * CATT + 255) / 256, 256>>>(w_proj, wph, wpl, 256 * CATT);
    {
        dim3 grid(HWN / 32, CIN / 64, BATCH);
        transpose_split_x<<<grid, 256>>>(x, xh, xl);
    }

    // 1) qkv GEMM (fp16 split, k16 path): M=768, K=256
    {
        dim3 grid(HWN / 128, C3 / 128, BATCH);   // (32, 6, 16)
        gemm_f16<<<grid, 256>>>(wqh, wql, xh, xl, qkv_s, C3, CIN);
    }

    // 2+3) fused depthwise 5x5 + grouped pointwise -> agg
    {
        dim3 grid(4, PWG, BATCH);                // (4, 96, 16)
        dwpw<<<grid, 256>>>(qkv_s, w_dw, w_pw, agg_s);
    }

    // 4) attention -> transposed bf16 hi/lo
    relu_lin_att<<<BATCH * 64, 256>>>(qkv_s, agg_s, ah, al);

    // 5) proj GEMM (bf16 split) + BN: M=256, K=512
    {
        dim3 grid(HWN / 128, 256 / 128, BATCH);  // (32, 2, 16)
        gemm_mma<<<grid, 256>>>(wph, wpl, ah, al, out, 256, CATT,
                                gamma, beta, mean, var);
    }
}

// round 12
// speedup vs baseline: 1.8527x; 1.0144x over previous
#include <cuda_runtime.h>
#include <cuda_bf16.h>
#include <cuda_fp16.h>
#include <cstdint>

// Problem constants
#define BATCH 16
#define CIN   256
#define HWN   4096          // 64*64
#define C3    768           // 3*TOTAL
#define CATT  512           // 2*TOTAL
#define PWG   96

// ---------------------------------------------------------------------------
// Scratch (static device memory)
// ---------------------------------------------------------------------------
__device__ float g_qkv[BATCH * C3 * HWN];               // 201 MB
__device__ float g_agg[BATCH * C3 * HWN];               // 201 MB
__device__ __half g_xT_hi[BATCH * HWN * CIN];           // 33.5 MB
__device__ __half g_xT_lo[BATCH * HWN * CIN];
__device__ __nv_bfloat16 g_attT_hi[BATCH * HWN * CATT]; // 67 MB
__device__ __nv_bfloat16 g_attT_lo[BATCH * HWN * CATT];
__device__ __half g_wqkv_hi[C3 * CIN];
__device__ __half g_wqkv_lo[C3 * CIN];
__device__ __nv_bfloat16 g_wproj_hi[256 * CATT];
__device__ __nv_bfloat16 g_wproj_lo[256 * CATT];

// ---------------------------------------------------------------------------
// Helpers
// ---------------------------------------------------------------------------
__device__ __forceinline__ uint32_t smem_u32(const void* p) {
    uint32_t a;
    asm("{ .reg .u64 t; cvta.to.shared.u64 t, %1; cvt.u32.u64 %0, t; }" : "=r"(a) : "l"(p));
    return a;
}
__device__ __forceinline__ void ldmx4(uint32_t* r, uint32_t addr) {
    asm volatile("ldmatrix.sync.aligned.m8n8.x4.shared.b16 {%0,%1,%2,%3}, [%4];"
                 : "=r"(r[0]), "=r"(r[1]), "=r"(r[2]), "=r"(r[3]) : "r"(addr));
}
__device__ __forceinline__ void ldmx2(uint32_t* r, uint32_t addr) {
    asm volatile("ldmatrix.sync.aligned.m8n8.x2.shared.b16 {%0,%1}, [%2];"
                 : "=r"(r[0]), "=r"(r[1]) : "r"(addr));
}
__device__ __forceinline__ void mma_bf16(float* d, const uint32_t* a, const uint32_t* b) {
    asm volatile(
        "mma.sync.aligned.m16n8k16.row.col.f32.bf16.bf16.f32 "
        "{%0,%1,%2,%3}, {%4,%5,%6,%7}, {%8,%9}, {%0,%1,%2,%3};"
        : "+f"(d[0]), "+f"(d[1]), "+f"(d[2]), "+f"(d[3])
        : "r"(a[0]), "r"(a[1]), "r"(a[2]), "r"(a[3]), "r"(b[0]), "r"(b[1]));
}
__device__ __forceinline__ void mma_f16(float* d, const uint32_t* a, const uint32_t* b) {
    asm volatile(
        "mma.sync.aligned.m16n8k16.row.col.f32.f16.f16.f32 "
        "{%0,%1,%2,%3}, {%4,%5,%6,%7}, {%8,%9}, {%0,%1,%2,%3};"
        : "+f"(d[0]), "+f"(d[1]), "+f"(d[2]), "+f"(d[3])
        : "r"(a[0]), "r"(a[1]), "r"(a[2]), "r"(a[3]), "r"(b[0]), "r"(b[1]));
}
__device__ __forceinline__ void cp_async16(uint32_t saddr, const void* gaddr) {
    asm volatile("cp.async.cg.shared.global [%0], [%1], 16;" :: "r"(saddr), "l"(gaddr) : "memory");
}
__device__ __forceinline__ void cp_commit() {
    asm volatile("cp.async.commit_group;" ::: "memory");
}
__device__ __forceinline__ void cp_wait1() {
    asm volatile("cp.async.wait_group 1;" ::: "memory");
}
__device__ __forceinline__ void cp_wait0() {
    asm volatile("cp.async.wait_group 0;" ::: "memory");
}

// ---------------------------------------------------------------------------
// Splits
// ---------------------------------------------------------------------------
__global__ void split_bf16(const float* __restrict__ src,
                           __nv_bfloat16* __restrict__ hi,
                           __nv_bfloat16* __restrict__ lo, int n) {
    int i = blockIdx.x * 256 + threadIdx.x;
    if (i < n) {
        float v = src[i];
        __nv_bfloat16 h = __float2bfloat16(v);
        hi[i] = h;
        lo[i] = __float2bfloat16(v - __bfloat162float(h));
    }
}
__global__ void split_f16(const float* __restrict__ src,
                          __half* __restrict__ hi, __half* __restrict__ lo, int n) {
    int i = blockIdx.x * 256 + threadIdx.x;
    if (i < n) {
        float v = src[i];
        __half h = __float2half_rn(v);
        hi[i] = h;
        lo[i] = __float2half_rn(v - __half2float(h));
    }
}

// ---------------------------------------------------------------------------
// Transpose + fp16-split x: [b][c][n] fp32 -> xT_hi/lo [b][n][c]
// ---------------------------------------------------------------------------
__global__ __launch_bounds__(256) void transpose_split_x(
    const float* __restrict__ x, __half* __restrict__ xhi, __half* __restrict__ xlo) {
    const int b = blockIdx.z;
    const int c0 = blockIdx.y * 64;
    const int n0 = blockIdx.x * 32;
    __shared__ float s[64][33];
    const int tid = threadIdx.x;
#pragma unroll
    for (int i = 0; i < 8; i++) {
        int u = tid + 256 * i;
        int cc = u >> 5, nn = u & 31;
        s[cc][nn] = x[((size_t)b * CIN + c0 + cc) * HWN + n0 + nn];
    }
    __syncthreads();
#pragma unroll
    for (int i = 0; i < 8; i++) {
        int u = tid + 256 * i;
        int cc = u & 63, nn = u >> 6;
        float v = s[cc][nn];
        __half h = __float2half_rn(v);
        size_t idx = ((size_t)b * HWN + n0 + nn) * CIN + c0 + cc;
        xhi[idx] = h;
        xlo[idx] = __float2half_rn(v - __half2float(h));
    }
}

// ---------------------------------------------------------------------------
// fp16 3-term split GEMM (qkv) with cp.async 2-stage pipeline.
// 256 thr, 8 warps (2x4), warp 64x32, BK=32, LDS=40 pad, ldmatrix fragments.
// Dynamic smem: 2 stages x 4 arrays x 128*LDS halves = 81920 B.
// ---------------------------------------------------------------------------
#define BK  32
#define LDS 40
#define TILE_E (128 * LDS)          // elements per array
#define STAGE_E (4 * TILE_E)        // elements per stage
#define GEMM_DSMEM (2 * STAGE_E * 2) // bytes (2B elements)

__global__ __launch_bounds__(256, 2) void gemm_f16(
    const __half* __restrict__ Ahi, const __half* __restrict__ Alo,
    const __half* __restrict__ Bhi, const __half* __restrict__ Blo,
    float* __restrict__ Cg, int M, int K) {
    extern __shared__ __half sm_h[];

    const int tid = threadIdx.x;
    const int wid = tid >> 5;
    const int lane = tid & 31;

    const int b = blockIdx.z;
    const int m0 = blockIdx.y * 128;
    const int n0 = blockIdx.x * 128;

    const __half* Bh = Bhi + (size_t)b * HWN * K;
    const __half* Bl = Blo + (size_t)b * HWN * K;

    const int wm = (wid >> 2) * 64;
    const int wn = (wid & 3) * 32;

    const int ar = lane & 15, ac = (lane >> 4) << 3;
    const int br = lane & 7,  bc = ((lane >> 3) & 1) << 3;

    // per-thread load coordinates (2 x 16B per array per chunk)
    const int lrow0 = tid >> 1;                 // rows 0..127 (i=0)
    const int lcu0 = (tid & 1) << 4;            // 0 or 16
    const uint32_t sb0 = smem_u32(sm_h);

    float acc[4][4][4];
#pragma unroll
    for (int mt = 0; mt < 4; mt++)
#pragma unroll
        for (int nt = 0; nt < 4; nt++)
#pragma unroll
            for (int r = 0; r < 4; r++) acc[mt][nt][r] = 0.f;

    const int nch = K / BK;

    // chunk loader: issues 8 cp.async (16B) into stage st
    auto load_chunk = [&](int c, int st) {
        const int kc = c * BK;
        uint32_t base = sb0 + (uint32_t)(st * STAGE_E) * 2;
#pragma unroll
        for (int i = 0; i < 2; i++) {
            int row = lrow0;            // same row, two 16B pieces? no:
            int cu = lcu0;
            // thread covers (row, cu) and (row+? ) — regenerate from u
            int u = tid + 256 * i;      // 0..511
            row = u >> 2;
            cu = (u & 3) << 3;          // 0,8,16,24
            uint32_t so = (uint32_t)(row * LDS + cu) * 2;
            cp_async16(base + 0 * TILE_E * 2 + so, Ahi + (size_t)(m0 + row) * K + kc + cu);
            cp_async16(base + 1 * TILE_E * 2 + so, Alo + (size_t)(m0 + row) * K + kc + cu);
            cp_async16(base + 2 * TILE_E * 2 + so, Bh + (size_t)(n0 + row) * K + kc + cu);
            cp_async16(base + 3 * TILE_E * 2 + so, Bl + (size_t)(n0 + row) * K + kc + cu);
        }
        cp_commit();
    };

    load_chunk(0, 0);

    for (int c = 0; c < nch; c++) {
        const int st = c & 1;
        if (c + 1 < nch) load_chunk(c + 1, (c + 1) & 1);
        if (c + 1 < nch) cp_wait1(); else cp_wait0();
        __syncthreads();

        const __half* As_hi = sm_h + st * STAGE_E + 0 * TILE_E;
        const __half* As_lo = sm_h + st * STAGE_E + 1 * TILE_E;
        const __half* Bs_hi = sm_h + st * STAGE_E + 2 * TILE_E;
        const __half* Bs_lo = sm_h + st * STAGE_E + 3 * TILE_E;

#pragma unroll
        for (int kk = 0; kk < BK; kk += 16) {
            uint32_t ah[4][4], bhf[4][2];
#pragma unroll
            for (int mt = 0; mt < 4; mt++)
                ldmx4(ah[mt], smem_u32(&As_hi[(wm + mt * 16 + ar) * LDS + kk + ac]));
#pragma unroll
            for (int nt = 0; nt < 4; nt++)
                ldmx2(bhf[nt], smem_u32(&Bs_hi[(wn + nt * 8 + br) * LDS + kk + bc]));
#pragma unroll
            for (int mt = 0; mt < 4; mt++)
#pragma unroll
                for (int nt = 0; nt < 4; nt++)
                    mma_f16(acc[mt][nt], ah[mt], bhf[nt]);

            uint32_t al[4][4];
#pragma unroll
            for (int mt = 0; mt < 4; mt++)
                ldmx4(al[mt], smem_u32(&As_lo[(wm + mt * 16 + ar) * LDS + kk + ac]));
#pragma unroll
            for (int mt = 0; mt < 4; mt++)
#pragma unroll
                for (int nt = 0; nt < 4; nt++)
                    mma_f16(acc[mt][nt], al[mt], bhf[nt]);

            uint32_t blf[4][2];
#pragma unroll
            for (int nt = 0; nt < 4; nt++)
                ldmx2(blf[nt], smem_u32(&Bs_lo[(wn + nt * 8 + br) * LDS + kk + bc]));
#pragma unroll
            for (int mt = 0; mt < 4; mt++)
#pragma unroll
                for (int nt = 0; nt < 4; nt++)
                    mma_f16(acc[mt][nt], ah[mt], blf[nt]);
        }
        __syncthreads();
    }

#pragma unroll
    for (int mt = 0; mt < 4; mt++) {
        const int row0 = m0 + wm + mt * 16 + (lane >> 2);
        const int row1 = row0 + 8;
        float* c0p = Cg + ((size_t)b * M + row0) * HWN + n0 + wn;
        float* c1p = Cg + ((size_t)b * M + row1) * HWN + n0 + wn;
        const int coff = ((lane & 3) << 1);
#pragma unroll
        for (int nt = 0; nt < 4; nt++) {
            *(float2*)(c0p + nt * 8 + coff) = make_float2(acc[mt][nt][0], acc[mt][nt][1]);
            *(float2*)(c1p + nt * 8 + coff) = make_float2(acc[mt][nt][2], acc[mt][nt][3]);
        }
    }
}

// ---------------------------------------------------------------------------
// bf16 3-term split GEMM (proj) with cp.async 2-stage pipeline + BN epilogue.
// ---------------------------------------------------------------------------
__global__ __launch_bounds__(256, 2) void gemm_mma(
    const __nv_bfloat16* __restrict__ Ahi, const __nv_bfloat16* __restrict__ Alo,
    const __nv_bfloat16* __restrict__ Bhi, const __nv_bfloat16* __restrict__ Blo,
    float* __restrict__ Cg, int M, int K,
    const float* __restrict__ gamma, const float* __restrict__ beta,
    const float* __restrict__ mean, const float* __restrict__ var) {
    extern __shared__ __nv_bfloat16 sm_b[];

    const int tid = threadIdx.x;
    const int wid = tid >> 5;
    const int lane = tid & 31;

    const int b = blockIdx.z;
    const int m0 = blockIdx.y * 128;
    const int n0 = blockIdx.x * 128;

    const __nv_bfloat16* Bh = Bhi + (size_t)b * HWN * K;
    const __nv_bfloat16* Bl = Blo + (size_t)b * HWN * K;

    const int wm = (wid >> 2) * 64;
    const int wn = (wid & 3) * 32;

    const int ar = lane & 15, ac = (lane >> 4) << 3;
    const int br = lane & 7,  bc = ((lane >> 3) & 1) << 3;

    const uint32_t sb0 = smem_u32(sm_b);

    float acc[4][4][4];
#pragma unroll
    for (int mt = 0; mt < 4; mt++)
#pragma unroll
        for (int nt = 0; nt < 4; nt++)
#pragma unroll
            for (int r = 0; r < 4; r++) acc[mt][nt][r] = 0.f;

    const int nch = K / BK;

    auto load_chunk = [&](int c, int st) {
        const int kc = c * BK;
        uint32_t base = sb0 + (uint32_t)(st * STAGE_E) * 2;
#pragma unroll
        for (int i = 0; i < 2; i++) {
            int u = tid + 256 * i;
            int row = u >> 2;
            int cu = (u & 3) << 3;
            uint32_t so = (uint32_t)(row * LDS + cu) * 2;
            cp_async16(base + 0 * TILE_E * 2 + so, Ahi + (size_t)(m0 + row) * K + kc + cu);
            cp_async16(base + 1 * TILE_E * 2 + so, Alo + (size_t)(m0 + row) * K + kc + cu);
            cp_async16(base + 2 * TILE_E * 2 + so, Bh + (size_t)(n0 + row) * K + kc + cu);
            cp_async16(base + 3 * TILE_E * 2 + so, Bl + (size_t)(n0 + row) * K + kc + cu);
        }
        cp_commit();
    };

    load_chunk(0, 0);

    for (int c = 0; c < nch; c++) {
        const int st = c & 1;
        if (c + 1 < nch) load_chunk(c + 1, (c + 1) & 1);
        if (c + 1 < nch) cp_wait1(); else cp_wait0();
        __syncthreads();

        const __nv_bfloat16* As_hi = sm_b + st * STAGE_E + 0 * TILE_E;
        const __nv_bfloat16* As_lo = sm_b + st * STAGE_E + 1 * TILE_E;
        const __nv_bfloat16* Bs_hi = sm_b + st * STAGE_E + 2 * TILE_E;
        const __nv_bfloat16* Bs_lo = sm_b + st * STAGE_E + 3 * TILE_E;

#pragma unroll
        for (int kk = 0; kk < BK; kk += 16) {
            uint32_t ah[4][4], bhf[4][2];
#pragma unroll
            for (int mt = 0; mt < 4; mt++)
                ldmx4(ah[mt], smem_u32(&As_hi[(wm + mt * 16 + ar) * LDS + kk + ac]));
#pragma unroll
            for (int nt = 0; nt < 4; nt++)
                ldmx2(bhf[nt], smem_u32(&Bs_hi[(wn + nt * 8 + br) * LDS + kk + bc]));
#pragma unroll
            for (int mt = 0; mt < 4; mt++)
#pragma unroll
                for (int nt = 0; nt < 4; nt++)
                    mma_bf16(acc[mt][nt], ah[mt], bhf[nt]);

            uint32_t al[4][4];
#pragma unroll
            for (int mt = 0; mt < 4; mt++)
                ldmx4(al[mt], smem_u32(&As_lo[(wm + mt * 16 + ar) * LDS + kk + ac]));
#pragma unroll
            for (int mt = 0; mt < 4; mt++)
#pragma unroll
                for (int nt = 0; nt < 4; nt++)
                    mma_bf16(acc[mt][nt], al[mt], bhf[nt]);

            uint32_t blf[4][2];
#pragma unroll
            for (int nt = 0; nt < 4; nt++)
                ldmx2(blf[nt], smem_u32(&Bs_lo[(wn + nt * 8 + br) * LDS + kk + bc]));
#pragma unroll
            for (int mt = 0; mt < 4; mt++)
#pragma unroll
                for (int nt = 0; nt < 4; nt++)
                    mma_bf16(acc[mt][nt], ah[mt], blf[nt]);
        }
        __syncthreads();
    }

#pragma unroll
    for (int mt = 0; mt < 4; mt++) {
        const int row0 = m0 + wm + mt * 16 + (lane >> 2);
        const int row1 = row0 + 8;
        float s0 = 1.f, o0 = 0.f, s1 = 1.f, o1 = 0.f;
        if (gamma) {
            float iv0 = gamma[row0] * rsqrtf(var[row0] + 1e-5f);
            s0 = iv0; o0 = beta[row0] - mean[row0] * iv0;
            float iv1 = gamma[row1] * rsqrtf(var[row1] + 1e-5f);
            s1 = iv1; o1 = beta[row1] - mean[row1] * iv1;
        }
        float* c0p = Cg + ((size_t)b * M + row0) * HWN + n0 + wn;
        float* c1p = Cg + ((size_t)b * M + row1) * HWN + n0 + wn;
        const int coff = ((lane & 3) << 1);
#pragma unroll
        for (int nt = 0; nt < 4; nt++) {
            float2 v0, v1;
            v0.x = acc[mt][nt][0] * s0 + o0;
            v0.y = acc[mt][nt][1] * s0 + o0;
            v1.x = acc[mt][nt][2] * s1 + o1;
            v1.y = acc[mt][nt][3] * s1 + o1;
            *(float2*)(c0p + nt * 8 + coff) = v0;
            *(float2*)(c1p + nt * 8 + coff) = v1;
        }
    }
}

// ---------------------------------------------------------------------------
// FUSED depthwise 5x5 (pad 2) + grouped 1x1 (8-ch groups).
// ---------------------------------------------------------------------------
__global__ __launch_bounds__(256) void dwpw(
    const float* __restrict__ qkv, const float* __restrict__ w_dw,
    const float* __restrict__ w_pw, float* __restrict__ agg) {
    const int tile = blockIdx.x;           // 0..3
    const int g = blockIdx.y;              // 0..95
    const int b = blockIdx.z;
    const int ty = (tile >> 1) * 32;
    const int tx = (tile & 1) * 32;

    __shared__ float h[8][36 * 36];
    __shared__ float wd[8][25];
    __shared__ float wp[64];

    const int tid = threadIdx.x;
    if (tid < 64) wp[tid] = w_pw[g * 64 + tid];
    if (tid < 200) {
        int c = tid / 25, t = tid % 25;
        wd[c][t] = w_dw[(g * 8 + c) * 25 + t];
    }

    const float* ip = qkv + ((size_t)b * C3 + (size_t)g * 8) * HWN;
    for (int idx = tid; idx < 8 * 1296; idx += 256) {
        int c = idx / 1296, rem = idx - c * 1296;
        int hy = rem / 36, hx = rem - hy * 36;
        int gy = ty + hy - 2, gx = tx + hx - 2;
        float v = 0.f;
        if ((unsigned)gy < 64u && (unsigned)gx < 64u) v = ip[(size_t)c * HWN + gy * 64 + gx];
        h[c][rem] = v;
    }
    __syncthreads();

    const int lx = tid & 31;
    const int sy = (tid >> 5) << 2;

    float d[8][4];
#pragma unroll
    for (int c = 0; c < 8; c++) {
        float a0 = 0.f, a1 = 0.f, a2 = 0.f, a3 = 0.f;
#pragma unroll
        for (int r = 0; r < 8; r++) {
            const float* hp = &h[c][(sy + r) * 36 + lx];
            float v0 = hp[0], v1 = hp[1], v2 = hp[2], v3 = hp[3], v4 = hp[4];
#pragma unroll
            for (int j = 0; j < 4; j++) {
                int dy = r - j;
                if (dy >= 0 && dy < 5) {
                    float s = v0 * wd[c][dy * 5 + 0];
                    s = fmaf(v1, wd[c][dy * 5 + 1], s);
                    s = fmaf(v2, wd[c][dy * 5 + 2], s);
                    s = fmaf(v3, wd[c][dy * 5 + 3], s);
                    s = fmaf(v4, wd[c][dy * 5 + 4], s);
                    if (j == 0) a0 += s;
                    else if (j == 1) a1 += s;
                    else if (j == 2) a2 += s;
                    else a3 += s;
                }
            }
        }
        d[c][0] = a0; d[c][1] = a1; d[c][2] = a2; d[c][3] = a3;
    }

    float* op = agg + ((size_t)b * C3 + (size_t)g * 8) * HWN;
#pragma unroll
    for (int j = 0; j < 4; j++) {
        size_t pbase = (size_t)(ty + sy + j) * 64 + tx + lx;
#pragma unroll
        for (int o = 0; o < 8; o++) {
            float s = 0.f;
#pragma unroll
            for (int c = 0; c < 8; c++) s = fmaf(wp[o * 8 + c], d[c][j], s);
            op[(size_t)o * HWN + pbase] = s;
        }
    }
}

// ---------------------------------------------------------------------------
// ReLU linear attention (proven R8 version).
// ---------------------------------------------------------------------------
__global__ __launch_bounds__(256) void relu_lin_att(
    const float* __restrict__ qkv, const float* __restrict__ agg,
    __nv_bfloat16* __restrict__ ohi, __nv_bfloat16* __restrict__ olo) {
    const int bg = blockIdx.x;
    const int b = bg >> 6;
    const int g = bg & 63;
    const float* base = (g < 32)
        ? qkv + ((size_t)b * C3 + (size_t)g * 24) * HWN
        : agg + ((size_t)b * C3 + (size_t)(g - 32) * 24) * HWN;

    __shared__ float kvs[72];
    const int tid = threadIdx.x;
    const int w = tid >> 5;
    const int lane = tid & 31;

    float kvr[9];
#pragma unroll
    for (int i = 0; i < 9; i++) kvr[i] = 0.f;

    const float* kch = base + (size_t)(8 + w) * HWN;
    for (int n4 = lane * 4; n4 < HWN; n4 += 128) {
        float4 kk = *(const float4*)(kch + n4);
        kk.x = fmaxf(kk.x, 0.f); kk.y = fmaxf(kk.y, 0.f);
        kk.z = fmaxf(kk.z, 0.f); kk.w = fmaxf(kk.w, 0.f);
#pragma unroll
        for (int e = 0; e < 8; e++) {
            float4 vv = *(const float4*)(base + (size_t)(16 + e) * HWN + n4);
            kvr[e] = fmaf(kk.x, vv.x, kvr[e]);
            kvr[e] = fmaf(kk.y, vv.y, kvr[e]);
            kvr[e] = fmaf(kk.z, vv.z, kvr[e]);
            kvr[e] = fmaf(kk.w, vv.w, kvr[e]);
        }
        kvr[8] += kk.x + kk.y + kk.z + kk.w;
    }
#pragma unroll
    for (int i = 0; i < 9; i++) {
        float v = kvr[i];
        v += __shfl_xor_sync(0xffffffffu, v, 16);
        v += __shfl_xor_sync(0xffffffffu, v, 8);
        v += __shfl_xor_sync(0xffffffffu, v, 4);
        v += __shfl_xor_sync(0xffffffffu, v, 2);
        v += __shfl_xor_sync(0xffffffffu, v, 1);
        if (lane == 0) kvs[w * 9 + i] = v;
    }
    __syncthreads();

    for (int n4 = tid * 4; n4 < HWN; n4 += 1024) {
        float4 q4[8];
#pragma unroll
        for (int d0 = 0; d0 < 8; d0++) {
            float4 q = *(const float4*)(base + (size_t)d0 * HWN + n4);
            q.x = fmaxf(q.x, 0.f); q.y = fmaxf(q.y, 0.f);
            q.z = fmaxf(q.z, 0.f); q.w = fmaxf(q.w, 0.f);
            q4[d0] = q;
        }
#pragma unroll
        for (int px = 0; px < 4; px++) {
            float qd[8];
#pragma unroll
            for (int d0 = 0; d0 < 8; d0++)
                qd[d0] = px == 0 ? q4[d0].x : px == 1 ? q4[d0].y : px == 2 ? q4[d0].z : q4[d0].w;
            float den = 0.f;
#pragma unroll
            for (int d0 = 0; d0 < 8; d0++) den = fmaf(qd[d0], kvs[d0 * 9 + 8], den);
            float rden = 1.f / (den + 1e-15f);
            __align__(16) __nv_bfloat16 hi[8], lo[8];
#pragma unroll
            for (int e = 0; e < 8; e++) {
                float num = 0.f;
#pragma unroll
                for (int d0 = 0; d0 < 8; d0++) num = fmaf(qd[d0], kvs[d0 * 9 + e], num);
                float v = num * rden;
                __nv_bfloat16 hh = __float2bfloat16(v);
                hi[e] = hh;
                lo[e] = __float2bfloat16(v - __bfloat162float(hh));
            }
            size_t idx = ((size_t)b * HWN + n4 + px) * CATT + g * 8;
            *(uint4*)(ohi + idx) = *(const uint4*)hi;
            *(uint4*)(olo + idx) = *(const uint4*)lo;
        }
    }
}

// ---------------------------------------------------------------------------
// Launch
// ---------------------------------------------------------------------------
extern "C" void kernel_launch(void* const* d_in, const int* in_sizes, int n_in,
                              void* d_out, int out_size) {
    const float* x      = (const float*)d_in[0];
    const float* w_qkv  = (const float*)d_in[1];
    const float* w_dw   = (const float*)d_in[2];
    const float* w_pw   = (const float*)d_in[3];
    const float* w_proj = (const float*)d_in[4];
    const float* gamma  = (const float*)d_in[5];
    const float* beta   = (const float*)d_in[6];
    const float* mean   = (const float*)d_in[7];
    const float* var    = (const float*)d_in[8];
    float* out = (float*)d_out;

    float *qkv_s, *agg_s;
    __half *xh, *xl, *wqh, *wql;
    __nv_bfloat16 *ah, *al, *wph, *wpl;
    cudaGetSymbolAddress((void**)&qkv_s, g_qkv);
    cudaGetSymbolAddress((void**)&agg_s, g_agg);
    cudaGetSymbolAddress((void**)&xh, g_xT_hi);
    cudaGetSymbolAddress((void**)&xl, g_xT_lo);
    cudaGetSymbolAddress((void**)&ah, g_attT_hi);
    cudaGetSymbolAddress((void**)&al, g_attT_lo);
    cudaGetSymbolAddress((void**)&wqh, g_wqkv_hi);
    cudaGetSymbolAddress((void**)&wql, g_wqkv_lo);
    cudaGetSymbolAddress((void**)&wph, g_wproj_hi);
    cudaGetSymbolAddress((void**)&wpl, g_wproj_lo);

    static bool attr_set = false;
    if (!attr_set) {
        cudaFuncSetAttribute(gemm_f16, cudaFuncAttributeMaxDynamicSharedMemorySize, GEMM_DSMEM);
        cudaFuncSetAttribute(gemm_mma, cudaFuncAttributeMaxDynamicSharedMemorySize, GEMM_DSMEM);
        attr_set = true;
    }

    // 0) weight splits + x transpose/split
    split_f16<<<(C3 * CIN + 255) / 256, 256>>>(w_qkv, wqh, wql, C3 * CIN);
    split_bf16<<<(256 * CATT + 255) / 256, 256>>>(w_proj, wph, wpl, 256 * CATT);
    {
        dim3 grid(HWN / 32, CIN / 64, BATCH);
        transpose_split_x<<<grid, 256>>>(x, xh, xl);
    }

    // 1) qkv GEMM (fp16 split, cp.async pipelined): M=768, K=256
    {
        dim3 grid(HWN / 128, C3 / 128, BATCH);   // (32, 6, 16)
        gemm_f16<<<grid, 256, GEMM_DSMEM>>>(wqh, wql, xh, xl, qkv_s, C3, CIN);
    }

    // 2+3) fused depthwise 5x5 + grouped pointwise -> agg
    {
        dim3 grid(4, PWG, BATCH);                // (4, 96, 16)
        dwpw<<<grid, 256>>>(qkv_s, w_dw, w_pw, agg_s);
    }

    // 4) attention -> transposed bf16 hi/lo
    relu_lin_att<<<BATCH * 64, 256>>>(qkv_s, agg_s, ah, al);

    // 5) proj GEMM (bf16 split, cp.async pipelined) + BN: M=256, K=512
    {
        dim3 grid(HWN / 128, 256 / 128, BATCH);  // (32, 2, 16)
        gemm_mma<<<grid, 256, GEMM_DSMEM>>>(wph, wpl, ah, al, out, 256, CATT,
                                            gamma, beta, mean, var);
    }
}

// round 13
// speedup vs baseline: 1.9869x; 1.0724x over previous
#include <cuda_runtime.h>
#include <cuda_fp16.h>
#include <cstdint>

// Problem constants
#define BATCH 16
#define CIN   256
#define HWN   4096          // 64*64
#define C3    768           // 3*TOTAL
#define CATT  512           // 2*TOTAL
#define PWG   96

// ---------------------------------------------------------------------------
// Scratch (static device memory)
// ---------------------------------------------------------------------------
__device__ float g_qkv[BATCH * C3 * HWN];               // 201 MB
__device__ float g_agg[BATCH * C3 * HWN];               // 201 MB
__device__ __half g_attT[BATCH * HWN * CATT];           // 67 MB (fp16, single)
__device__ __half g_wqkv_hi[C3 * CIN];
__device__ __half g_wqkv_lo[C3 * CIN];
__device__ __half g_wproj_hi[256 * CATT];
__device__ __half g_wproj_lo[256 * CATT];

// ---------------------------------------------------------------------------
// Helpers
// ---------------------------------------------------------------------------
__device__ __forceinline__ uint32_t smem_u32(const void* p) {
    uint32_t a;
    asm("{ .reg .u64 t; cvta.to.shared.u64 t, %1; cvt.u32.u64 %0, t; }" : "=r"(a) : "l"(p));
    return a;
}
__device__ __forceinline__ void ldmx4(uint32_t* r, uint32_t addr) {
    asm volatile("ldmatrix.sync.aligned.m8n8.x4.shared.b16 {%0,%1,%2,%3}, [%4];"
                 : "=r"(r[0]), "=r"(r[1]), "=r"(r[2]), "=r"(r[3]) : "r"(addr));
}
__device__ __forceinline__ void ldmx2(uint32_t* r, uint32_t addr) {
    asm volatile("ldmatrix.sync.aligned.m8n8.x2.shared.b16 {%0,%1}, [%2];"
                 : "=r"(r[0]), "=r"(r[1]) : "r"(addr));
}
__device__ __forceinline__ void mma_f16(float* d, const uint32_t* a, const uint32_t* b) {
    asm volatile(
        "mma.sync.aligned.m16n8k16.row.col.f32.f16.f16.f32 "
        "{%0,%1,%2,%3}, {%4,%5,%6,%7}, {%8,%9}, {%0,%1,%2,%3};"
        : "+f"(d[0]), "+f"(d[1]), "+f"(d[2]), "+f"(d[3])
        : "r"(a[0]), "r"(a[1]), "r"(a[2]), "r"(a[3]), "r"(b[0]), "r"(b[1]));
}

// ---------------------------------------------------------------------------
// fp16 weight split
// ---------------------------------------------------------------------------
__global__ void split_f16(const float* __restrict__ src,
                          __half* __restrict__ hi, __half* __restrict__ lo, int n) {
    int i = blockIdx.x * 256 + threadIdx.x;
    if (i < n) {
        float v = src[i];
        __half h = __float2half_rn(v);
        hi[i] = h;
        lo[i] = __float2half_rn(v - __half2float(h));
    }
}

// ---------------------------------------------------------------------------
// qkv GEMM: fp16 3-term split, fused x transpose+split in the B loader.
//   C[b][m][n] = sum_k A[m][k] * x[b][k][n]
// A: w_qkv hi/lo fp16 [M][K] K-major. x read directly as [b][c][n] fp32.
// 256 thr, 8 warps (2x4), warp 64x32, BK=32, LDS=40 pad, single-stage smem.
// ---------------------------------------------------------------------------
#define BK  32
#define LDS 40

__global__ __launch_bounds__(256, 2) void gemm_qkv(
    const __half* __restrict__ Ahi, const __half* __restrict__ Alo,
    const float* __restrict__ Xg, float* __restrict__ Cg, int M, int K) {
    __shared__ __half As_hi[128 * LDS];
    __shared__ __half As_lo[128 * LDS];
    __shared__ __half Bs_hi[128 * LDS];
    __shared__ __half Bs_lo[128 * LDS];

    const int tid = threadIdx.x;
    const int wid = tid >> 5;
    const int lane = tid & 31;

    const int b = blockIdx.z;
    const int m0 = blockIdx.y * 128;
    const int n0 = blockIdx.x * 128;

    const float* Xb = Xg + (size_t)b * CIN * HWN;

    const int wm = (wid >> 2) * 64;
    const int wn = (wid & 3) * 32;

    const int ar = lane & 15, ac = (lane >> 4) << 3;
    const int br = lane & 7,  bc = ((lane >> 3) & 1) << 3;

    // B loader coords: channel pair + 8-pixel group per thread
    const int pair = tid & 15;        // channel pair 0..15 (-> c = 2*pair, 2*pair+1)
    const int pgrp = tid >> 4;        // pixel group 0..15 (8 pixels each)

    float acc[4][4][4];
#pragma unroll
    for (int mt = 0; mt < 4; mt++)
#pragma unroll
        for (int nt = 0; nt < 4; nt++)
#pragma unroll
            for (int r = 0; r < 4; r++) acc[mt][nt][r] = 0.f;

    for (int kc = 0; kc < K; kc += BK) {
        // ---- A tile (weights, hi+lo): 128 rows x 32 halves each ----
#pragma unroll
        for (int i = 0; i < 2; i++) {
            int u = tid + 256 * i;
            int row = u >> 2;
            int cu = (u & 3) << 3;
            size_t sa = (size_t)(m0 + row) * K + kc + cu;
            *(uint4*)&As_hi[row * LDS + cu] = *(const uint4*)(Ahi + sa);
            *(uint4*)&As_lo[row * LDS + cu] = *(const uint4*)(Alo + sa);
        }
        // ---- B tile: transpose + fp16-split x on the fly ----
        {
            const float* x0 = Xb + (size_t)(kc + 2 * pair) * HWN + n0 + pgrp * 8;
            const float* x1 = x0 + HWN;
            float4 a0 = *(const float4*)(x0);
            float4 a1 = *(const float4*)(x0 + 4);
            float4 c0 = *(const float4*)(x1);
            float4 c1 = *(const float4*)(x1 + 4);
            float va[8] = {a0.x, a0.y, a0.z, a0.w, a1.x, a1.y, a1.z, a1.w};
            float vb[8] = {c0.x, c0.y, c0.z, c0.w, c1.x, c1.y, c1.z, c1.w};
#pragma unroll
            for (int i = 0; i < 8; i++) {
                __half h0 = __float2half_rn(va[i]);
                __half l0 = __float2half_rn(va[i] - __half2float(h0));
                __half h1 = __float2half_rn(vb[i]);
                __half l1 = __float2half_rn(vb[i] - __half2float(h1));
                int off = (pgrp * 8 + i) * LDS + 2 * pair;
                *(__half2*)&Bs_hi[off] = __halves2half2(h0, h1);
                *(__half2*)&Bs_lo[off] = __halves2half2(l0, l1);
            }
        }
        __syncthreads();

#pragma unroll
        for (int kk = 0; kk < BK; kk += 16) {
            uint32_t ah[4][4], bhf[4][2];
#pragma unroll
            for (int mt = 0; mt < 4; mt++)
                ldmx4(ah[mt], smem_u32(&As_hi[(wm + mt * 16 + ar) * LDS + kk + ac]));
#pragma unroll
            for (int nt = 0; nt < 4; nt++)
                ldmx2(bhf[nt], smem_u32(&Bs_hi[(wn + nt * 8 + br) * LDS + kk + bc]));
#pragma unroll
            for (int mt = 0; mt < 4; mt++)
#pragma unroll
                for (int nt = 0; nt < 4; nt++)
                    mma_f16(acc[mt][nt], ah[mt], bhf[nt]);

            uint32_t al[4][4];
#pragma unroll
            for (int mt = 0; mt < 4; mt++)
                ldmx4(al[mt], smem_u32(&As_lo[(wm + mt * 16 + ar) * LDS + kk + ac]));
#pragma unroll
            for (int mt = 0; mt < 4; mt++)
#pragma unroll
                for (int nt = 0; nt < 4; nt++)
                    mma_f16(acc[mt][nt], al[mt], bhf[nt]);

            uint32_t blf[4][2];
#pragma unroll
            for (int nt = 0; nt < 4; nt++)
                ldmx2(blf[nt], smem_u32(&Bs_lo[(wn + nt * 8 + br) * LDS + kk + bc]));
#pragma unroll
            for (int mt = 0; mt < 4; mt++)
#pragma unroll
                for (int nt = 0; nt < 4; nt++)
                    mma_f16(acc[mt][nt], ah[mt], blf[nt]);
        }
        __syncthreads();
    }

#pragma unroll
    for (int mt = 0; mt < 4; mt++) {
        const int row0 = m0 + wm + mt * 16 + (lane >> 2);
        const int row1 = row0 + 8;
        float* c0p = Cg + ((size_t)b * M + row0) * HWN + n0 + wn;
        float* c1p = Cg + ((size_t)b * M + row1) * HWN + n0 + wn;
        const int coff = ((lane & 3) << 1);
#pragma unroll
        for (int nt = 0; nt < 4; nt++) {
            *(float2*)(c0p + nt * 8 + coff) = make_float2(acc[mt][nt][0], acc[mt][nt][1]);
            *(float2*)(c1p + nt * 8 + coff) = make_float2(acc[mt][nt][2], acc[mt][nt][3]);
        }
    }
}

// ---------------------------------------------------------------------------
// proj GEMM: fp16 2-term split (w = hi+lo, att single fp16) + BN epilogue.
//   out[b][m][n] = BN(sum_k w[m][k] * att[b][n][k])
// ---------------------------------------------------------------------------
__global__ __launch_bounds__(256, 2) void gemm_proj(
    const __half* __restrict__ Ahi, const __half* __restrict__ Alo,
    const __half* __restrict__ Bg, float* __restrict__ Cg, int M, int K,
    const float* __restrict__ gamma, const float* __restrict__ beta,
    const float* __restrict__ mean, const float* __restrict__ var) {
    __shared__ __half As_hi[128 * LDS];
    __shared__ __half As_lo[128 * LDS];
    __shared__ __half Bs[128 * LDS];

    const int tid = threadIdx.x;
    const int wid = tid >> 5;
    const int lane = tid & 31;

    const int b = blockIdx.z;
    const int m0 = blockIdx.y * 128;
    const int n0 = blockIdx.x * 128;

    const __half* Bb = Bg + (size_t)b * HWN * K;

    const int wm = (wid >> 2) * 64;
    const int wn = (wid & 3) * 32;

    const int ar = lane & 15, ac = (lane >> 4) << 3;
    const int br = lane & 7,  bc = ((lane >> 3) & 1) << 3;

    float acc[4][4][4];
#pragma unroll
    for (int mt = 0; mt < 4; mt++)
#pragma unroll
        for (int nt = 0; nt < 4; nt++)
#pragma unroll
            for (int r = 0; r < 4; r++) acc[mt][nt][r] = 0.f;

    for (int kc = 0; kc < K; kc += BK) {
#pragma unroll
        for (int i = 0; i < 2; i++) {
            int u = tid + 256 * i;
            int row = u >> 2;
            int cu = (u & 3) << 3;
            size_t sa = (size_t)(m0 + row) * K + kc + cu;
            *(uint4*)&As_hi[row * LDS + cu] = *(const uint4*)(Ahi + sa);
            *(uint4*)&As_lo[row * LDS + cu] = *(const uint4*)(Alo + sa);
            size_t sb = (size_t)(n0 + row) * K + kc + cu;
            *(uint4*)&Bs[row * LDS + cu] = *(const uint4*)(Bb + sb);
        }
        __syncthreads();

#pragma unroll
        for (int kk = 0; kk < BK; kk += 16) {
            uint32_t ah[4][4], bf[4][2];
#pragma unroll
            for (int mt = 0; mt < 4; mt++)
                ldmx4(ah[mt], smem_u32(&As_hi[(wm + mt * 16 + ar) * LDS + kk + ac]));
#pragma unroll
            for (int nt = 0; nt < 4; nt++)
                ldmx2(bf[nt], smem_u32(&Bs[(wn + nt * 8 + br) * LDS + kk + bc]));
#pragma unroll
            for (int mt = 0; mt < 4; mt++)
#pragma unroll
                for (int nt = 0; nt < 4; nt++)
                    mma_f16(acc[mt][nt], ah[mt], bf[nt]);

            uint32_t al[4][4];
#pragma unroll
            for (int mt = 0; mt < 4; mt++)
                ldmx4(al[mt], smem_u32(&As_lo[(wm + mt * 16 + ar) * LDS + kk + ac]));
#pragma unroll
            for (int mt = 0; mt < 4; mt++)
#pragma unroll
                for (int nt = 0; nt < 4; nt++)
                    mma_f16(acc[mt][nt], al[mt], bf[nt]);
        }
        __syncthreads();
    }

#pragma unroll
    for (int mt = 0; mt < 4; mt++) {
        const int row0 = m0 + wm + mt * 16 + (lane >> 2);
        const int row1 = row0 + 8;
        float iv0 = gamma[row0] * rsqrtf(var[row0] + 1e-5f);
        float s0 = iv0, o0 = beta[row0] - mean[row0] * iv0;
        float iv1 = gamma[row1] * rsqrtf(var[row1] + 1e-5f);
        float s1 = iv1, o1 = beta[row1] - mean[row1] * iv1;
        float* c0p = Cg + ((size_t)b * M + row0) * HWN + n0 + wn;
        float* c1p = Cg + ((size_t)b * M + row1) * HWN + n0 + wn;
        const int coff = ((lane & 3) << 1);
#pragma unroll
        for (int nt = 0; nt < 4; nt++) {
            float2 v0, v1;
            v0.x = acc[mt][nt][0] * s0 + o0;
            v0.y = acc[mt][nt][1] * s0 + o0;
            v1.x = acc[mt][nt][2] * s1 + o1;
            v1.y = acc[mt][nt][3] * s1 + o1;
            *(float2*)(c0p + nt * 8 + coff) = v0;
            *(float2*)(c1p + nt * 8 + coff) = v1;
        }
    }
}

// ---------------------------------------------------------------------------
// FUSED depthwise 5x5 (pad 2) + grouped 1x1 (8-ch groups).
// ---------------------------------------------------------------------------
__global__ __launch_bounds__(256) void dwpw(
    const float* __restrict__ qkv, const float* __restrict__ w_dw,
    const float* __restrict__ w_pw, float* __restrict__ agg) {
    const int tile = blockIdx.x;
    const int g = blockIdx.y;
    const int b = blockIdx.z;
    const int ty = (tile >> 1) * 32;
    const int tx = (tile & 1) * 32;

    __shared__ float h[8][36 * 36];
    __shared__ float wd[8][25];
    __shared__ float wp[64];

    const int tid = threadIdx.x;
    if (tid < 64) wp[tid] = w_pw[g * 64 + tid];
    if (tid < 200) {
        int c = tid / 25, t = tid % 25;
        wd[c][t] = w_dw[(g * 8 + c) * 25 + t];
    }

    const float* ip = qkv + ((size_t)b * C3 + (size_t)g * 8) * HWN;
    for (int idx = tid; idx < 8 * 1296; idx += 256) {
        int c = idx / 1296, rem = idx - c * 1296;
        int hy = rem / 36, hx = rem - hy * 36;
        int gy = ty + hy - 2, gx = tx + hx - 2;
        float v = 0.f;
        if ((unsigned)gy < 64u && (unsigned)gx < 64u) v = ip[(size_t)c * HWN + gy * 64 + gx];
        h[c][rem] = v;
    }
    __syncthreads();

    const int lx = tid & 31;
    const int sy = (tid >> 5) << 2;

    float d[8][4];
#pragma unroll
    for (int c = 0; c < 8; c++) {
        float a0 = 0.f, a1 = 0.f, a2 = 0.f, a3 = 0.f;
#pragma unroll
        for (int r = 0; r < 8; r++) {
            const float* hp = &h[c][(sy + r) * 36 + lx];
            float v0 = hp[0], v1 = hp[1], v2 = hp[2], v3 = hp[3], v4 = hp[4];
#pragma unroll
            for (int j = 0; j < 4; j++) {
                int dy = r - j;
                if (dy >= 0 && dy < 5) {
                    float s = v0 * wd[c][dy * 5 + 0];
                    s = fmaf(v1, wd[c][dy * 5 + 1], s);
                    s = fmaf(v2, wd[c][dy * 5 + 2], s);
                    s = fmaf(v3, wd[c][dy * 5 + 3], s);
                    s = fmaf(v4, wd[c][dy * 5 + 4], s);
                    if (j == 0) a0 += s;
                    else if (j == 1) a1 += s;
                    else if (j == 2) a2 += s;
                    else a3 += s;
                }
            }
        }
        d[c][0] = a0; d[c][1] = a1; d[c][2] = a2; d[c][3] = a3;
    }

    float* op = agg + ((size_t)b * C3 + (size_t)g * 8) * HWN;
#pragma unroll
    for (int j = 0; j < 4; j++) {
        size_t pbase = (size_t)(ty + sy + j) * 64 + tx + lx;
#pragma unroll
        for (int o = 0; o < 8; o++) {
            float s = 0.f;
#pragma unroll
            for (int c = 0; c < 8; c++) s = fmaf(wp[o * 8 + c], d[c][j], s);
            op[(size_t)o * HWN + pbase] = s;
        }
    }
}

// ---------------------------------------------------------------------------
// ReLU linear attention; writes transposed fp16 output attT[b][n][g*8+e].
// ---------------------------------------------------------------------------
__global__ __launch_bounds__(256) void relu_lin_att(
    const float* __restrict__ qkv, const float* __restrict__ agg,
    __half* __restrict__ outp) {
    const int bg = blockIdx.x;
    const int b = bg >> 6;
    const int g = bg & 63;
    const float* base = (g < 32)
        ? qkv + ((size_t)b * C3 + (size_t)g * 24) * HWN
        : agg + ((size_t)b * C3 + (size_t)(g - 32) * 24) * HWN;

    __shared__ float kvs[72];
    const int tid = threadIdx.x;
    const int w = tid >> 5;
    const int lane = tid & 31;

    float kvr[9];
#pragma unroll
    for (int i = 0; i < 9; i++) kvr[i] = 0.f;

    const float* kch = base + (size_t)(8 + w) * HWN;
    for (int n4 = lane * 4; n4 < HWN; n4 += 128) {
        float4 kk = *(const float4*)(kch + n4);
        kk.x = fmaxf(kk.x, 0.f); kk.y = fmaxf(kk.y, 0.f);
        kk.z = fmaxf(kk.z, 0.f); kk.w = fmaxf(kk.w, 0.f);
#pragma unroll
        for (int e = 0; e < 8; e++) {
            float4 vv = *(const float4*)(base + (size_t)(16 + e) * HWN + n4);
            kvr[e] = fmaf(kk.x, vv.x, kvr[e]);
            kvr[e] = fmaf(kk.y, vv.y, kvr[e]);
            kvr[e] = fmaf(kk.z, vv.z, kvr[e]);
            kvr[e] = fmaf(kk.w, vv.w, kvr[e]);
        }
        kvr[8] += kk.x + kk.y + kk.z + kk.w;
    }
#pragma unroll
    for (int i = 0; i < 9; i++) {
        float v = kvr[i];
        v += __shfl_xor_sync(0xffffffffu, v, 16);
        v += __shfl_xor_sync(0xffffffffu, v, 8);
        v += __shfl_xor_sync(0xffffffffu, v, 4);
        v += __shfl_xor_sync(0xffffffffu, v, 2);
        v += __shfl_xor_sync(0xffffffffu, v, 1);
        if (lane == 0) kvs[w * 9 + i] = v;
    }
    __syncthreads();

    for (int n4 = tid * 4; n4 < HWN; n4 += 1024) {
        float4 q4[8];
#pragma unroll
        for (int d0 = 0; d0 < 8; d0++) {
            float4 q = *(const float4*)(base + (size_t)d0 * HWN + n4);
            q.x = fmaxf(q.x, 0.f); q.y = fmaxf(q.y, 0.f);
            q.z = fmaxf(q.z, 0.f); q.w = fmaxf(q.w, 0.f);
            q4[d0] = q;
        }
#pragma unroll
        for (int px = 0; px < 4; px++) {
            float qd[8];
#pragma unroll
            for (int d0 = 0; d0 < 8; d0++)
                qd[d0] = px == 0 ? q4[d0].x : px == 1 ? q4[d0].y : px == 2 ? q4[d0].z : q4[d0].w;
            float den = 0.f;
#pragma unroll
            for (int d0 = 0; d0 < 8; d0++) den = fmaf(qd[d0], kvs[d0 * 9 + 8], den);
            float rden = 1.f / (den + 1e-15f);
            __align__(16) __half o[8];
#pragma unroll
            for (int e = 0; e < 8; e++) {
                float num = 0.f;
#pragma unroll
                for (int d0 = 0; d0 < 8; d0++) num = fmaf(qd[d0], kvs[d0 * 9 + e], num);
                o[e] = __float2half_rn(num * rden);
            }
            size_t idx = ((size_t)b * HWN + n4 + px) * CATT + g * 8;
            *(uint4*)(outp + idx) = *(const uint4*)o;
        }
    }
}

// ---------------------------------------------------------------------------
// Launch
// ---------------------------------------------------------------------------
extern "C" void kernel_launch(void* const* d_in, const int* in_sizes, int n_in,
                              void* d_out, int out_size) {
    const float* x      = (const float*)d_in[0];
    const float* w_qkv  = (const float*)d_in[1];
    const float* w_dw   = (const float*)d_in[2];
    const float* w_pw   = (const float*)d_in[3];
    const float* w_proj = (const float*)d_in[4];
    const float* gamma  = (const float*)d_in[5];
    const float* beta   = (const float*)d_in[6];
    const float* mean   = (const float*)d_in[7];
    const float* var    = (const float*)d_in[8];
    float* out = (float*)d_out;

    float *qkv_s, *agg_s;
    __half *att, *wqh, *wql, *wph, *wpl;
    cudaGetSymbolAddress((void**)&qkv_s, g_qkv);
    cudaGetSymbolAddress((void**)&agg_s, g_agg);
    cudaGetSymbolAddress((void**)&att, g_attT);
    cudaGetSymbolAddress((void**)&wqh, g_wqkv_hi);
    cudaGetSymbolAddress((void**)&wql, g_wqkv_lo);
    cudaGetSymbolAddress((void**)&wph, g_wproj_hi);
    cudaGetSymbolAddress((void**)&wpl, g_wproj_lo);

    // 0) weight splits
    split_f16<<<(C3 * CIN + 255) / 256, 256>>>(w_qkv, wqh, wql, C3 * CIN);
    split_f16<<<(256 * CATT + 255) / 256, 256>>>(w_proj, wph, wpl, 256 * CATT);

    // 1) qkv GEMM (fp16 3-term split, fused x transpose): M=768, K=256
    {
        dim3 grid(HWN / 128, C3 / 128, BATCH);   // (32, 6, 16)
        gemm_qkv<<<grid, 256>>>(wqh, wql, x, qkv_s, C3, CIN);
    }

    // 2+3) fused depthwise 5x5 + grouped pointwise -> agg
    {
        dim3 grid(4, PWG, BATCH);                // (4, 96, 16)
        dwpw<<<grid, 256>>>(qkv_s, w_dw, w_pw, agg_s);
    }

    // 4) attention -> transposed fp16
    relu_lin_att<<<BATCH * 64, 256>>>(qkv_s, agg_s, att);

    // 5) proj GEMM (fp16 2-term split) + BN: M=256, K=512
    {
        dim3 grid(HWN / 128, 256 / 128, BATCH);  // (32, 2, 16)
        gemm_proj<<<grid, 256>>>(wph, wpl, att, out, 256, CATT,
                                 gamma, beta, mean, var);
    }
}